// round 13
// baseline (speedup 1.0000x reference)
#include <cuda_runtime.h>
#include <cuda_fp16.h>
#include <math.h>
#include <stdint.h>

// ---------------- problem constants ----------------
#define BATCH 2
#define SEQ   2048
#define T_TOK 4096
#define HIDN  2560
#define NH    32
#define NKV   8
#define HD    128
#define QDIM  4096
#define KVDIM 1024
#define QKVS  6144          // packed q|k|v row stride (halves)

// ---------------- scratch ----------------
__device__ __half g_hid_h[(size_t)T_TOK * HIDN];
__device__ __half g_WtAll[(size_t)QKVS * HIDN];   // WqT|WkT|WvT rows, each [*, 2560] K-major
__device__ __half g_WoT[(size_t)HIDN * QDIM];     // WoT [2560][4096] K-major
__device__ __half g_qkv[(size_t)T_TOK * QKVS];
__device__ __half g_ao[(size_t)T_TOK * QDIM];
__device__ float  g_cos[(size_t)T_TOK * 64];
__device__ float  g_sin[(size_t)T_TOK * 64];

// ---------------- helpers ----------------
__device__ __forceinline__ uint32_t smem_u32(const void* p) {
    uint32_t a;
    asm("{ .reg .u64 t; cvta.to.shared.u64 t, %1; cvt.u32.u64 %0, t; }" : "=r"(a) : "l"(p));
    return a;
}

__device__ __forceinline__ void cp16s(uint32_t saddr, const void* gsrc) {
    asm volatile("cp.async.cg.shared.global [%0], [%1], 16;\n" :: "r"(saddr), "l"(gsrc));
}

__device__ __forceinline__ void ldsm4(unsigned& r0, unsigned& r1, unsigned& r2, unsigned& r3,
                                      uint32_t addr) {
    asm volatile("ldmatrix.sync.aligned.m8n8.x4.shared.b16 {%0,%1,%2,%3}, [%4];"
                 : "=r"(r0), "=r"(r1), "=r"(r2), "=r"(r3) : "r"(addr));
}

__device__ __forceinline__ void ldsm4t(unsigned& r0, unsigned& r1, unsigned& r2, unsigned& r3,
                                       uint32_t addr) {
    asm volatile("ldmatrix.sync.aligned.m8n8.x4.trans.shared.b16 {%0,%1,%2,%3}, [%4];"
                 : "=r"(r0), "=r"(r1), "=r"(r2), "=r"(r3) : "r"(addr));
}

// m16n8k16 fp16 mma, fp32 accumulate
__device__ __forceinline__ void mma_f16(
    float& d0, float& d1, float& d2, float& d3,
    unsigned a0, unsigned a1, unsigned a2, unsigned a3,
    unsigned b0, unsigned b1)
{
    asm volatile(
        "mma.sync.aligned.m16n8k16.row.col.f32.f16.f16.f32 "
        "{%0,%1,%2,%3},{%4,%5,%6,%7},{%8,%9},{%0,%1,%2,%3};"
        : "+f"(d0), "+f"(d1), "+f"(d2), "+f"(d3)
        : "r"(a0), "r"(a1), "r"(a2), "r"(a3), "r"(b0), "r"(b1));
}

// ---------------- fp32 -> fp16 conversion ----------------
__global__ void conv_half_kernel(const float4* __restrict__ in, __half2* __restrict__ out, int n4) {
    int i = blockIdx.x * blockDim.x + threadIdx.x;
    int stride = gridDim.x * blockDim.x;
    for (; i < n4; i += stride) {
        float4 v = in[i];
        out[2 * i]     = __floats2half2_rn(v.x, v.y);
        out[2 * i + 1] = __floats2half2_rn(v.z, v.w);
    }
}

// ---------------- combined weight transpose + fp16 (all 4 weights, one launch) ----------
#define TRANS_BLOCKS 25600
__global__ void __launch_bounds__(256) transpose_all_kernel(
    const float* __restrict__ Wq, const float* __restrict__ Wk,
    const float* __restrict__ Wv, const float* __restrict__ Wo)
{
    int bid = blockIdx.x;
    const float* in;
    __half* out;
    int R, C;
    if (bid < 10240)      { in = Wq; out = g_WtAll;                         R = HIDN; C = QDIM;  }
    else if (bid < 12800) { in = Wk; out = g_WtAll + (size_t)4096 * HIDN;   R = HIDN; C = KVDIM; bid -= 10240; }
    else if (bid < 15360) { in = Wv; out = g_WtAll + (size_t)5120 * HIDN;   R = HIDN; C = KVDIM; bid -= 12800; }
    else                  { in = Wo; out = g_WoT;                           R = QDIM; C = HIDN;  bid -= 15360; }
    const int nbx = C / 32;
    const int bc = (bid % nbx) * 32, br = (bid / nbx) * 32;

    __shared__ float t[32][33];
    const int tx = threadIdx.x & 31, ty = threadIdx.x >> 5;   // 32 x 8
#pragma unroll
    for (int i = 0; i < 32; i += 8)
        t[ty + i][tx] = in[(size_t)(br + ty + i) * C + bc + tx];
    __syncthreads();
#pragma unroll
    for (int i = 0; i < 32; i += 8)
        out[(size_t)(bc + ty + i) * R + br + tx] = __float2half_rn(t[tx][ty + i]);
}

// ---------------- RoPE cos/sin table ----------------
__global__ void rope_table_kernel(const int* __restrict__ p32) {
    int idx = blockIdx.x * blockDim.x + threadIdx.x;
    if (idx >= T_TOK * 64) return;
    int t = idx >> 6;
    int i = idx & 63;
    bool is64 = (p32[1] == 0 && p32[2] == 1);
    int pos = is64 ? p32[2 * t] : p32[t];
    double ang = (double)pos * exp(-(double)i * (log(1000000.0) / 64.0));
    g_cos[idx] = (float)cos(ang);
    g_sin[idx] = (float)sin(ang);
}

// ---------------- fp16 mma GEMM: C[M,N] = A[M,K] @ Bt[N,K]^T ----------------
// 128-thread blocks, 2 blocks/SM (barrier decoupling). Block tile 128x128,
// 4 warps (2x2), warp tile 64x64, K-chunk 64, 2-stage cp.async pipeline.
#define TM 128
#define TN 128
#define GSTH 72
#define A_STAGE (TM * GSTH * 2)                 // 18432 B
#define STAGE_BYTES ((TM + TN) * GSTH * 2)      // 36864 B
#define GEMM_SMEM (2 * STAGE_BYTES)             // 73728 B -> 2 blocks/SM

__device__ __forceinline__ void g_load(
    const __half* __restrict__ A, const __half* __restrict__ Bt, int K,
    int mBase, int nBase, int kc, uint32_t sA, uint32_t sB, int tid)
{
    const __half* Ag = A + (size_t)mBase * K + (size_t)kc * 64;
#pragma unroll
    for (int i = 0; i < 8; i++) {
        int e = tid + i * 128;               // 128 rows x 8 chunks
        int r = e >> 3, q = (e & 7) << 3;    // q in halves
        cp16s(sA + (uint32_t)(r * GSTH + q) * 2, Ag + (size_t)r * K + q);
    }
    const __half* Bg = Bt + (size_t)nBase * K + (size_t)kc * 64;
#pragma unroll
    for (int i = 0; i < 8; i++) {
        int e = tid + i * 128;
        int r = e >> 3, q = (e & 7) << 3;
        cp16s(sB + (uint32_t)(r * GSTH + q) * 2, Bg + (size_t)r * K + q);
    }
    asm volatile("cp.async.commit_group;\n");
}

template <typename OutT>
__global__ void __launch_bounds__(128, 2) gemm_f16_kernel(
    const __half* __restrict__ A, const __half* __restrict__ Bt, OutT* __restrict__ C,
    int M, int N, int K)
{
    extern __shared__ char smem[];
    const uint32_t sb = smem_u32(smem);
    const int tid = threadIdx.x, warp = tid >> 5, lane = tid & 31;
    const int wm = warp >> 1, wn = warp & 1;       // 2 x 2 warp grid
    const int g = lane >> 2, tq = lane & 3;
    const int mBase = blockIdx.y * TM, nBase = blockIdx.x * TN;

    float c[4][8][4];
#pragma unroll
    for (int mt = 0; mt < 4; mt++)
#pragma unroll
        for (int nt = 0; nt < 8; nt++)
#pragma unroll
            for (int e = 0; e < 4; e++) c[mt][nt][e] = 0.f;

    const uint32_t aFragOff =
        (uint32_t)((wm * 64 + (lane & 15)) * GSTH) * 2 + ((lane & 16) ? 16u : 0u);
    const uint32_t bFragOff =
        (uint32_t)((wn * 64 + (lane & 7) + ((lane & 16) >> 1)) * GSTH) * 2 + ((lane & 8) << 1);

    const int nk = K >> 6;
    g_load(A, Bt, K, mBase, nBase, 0, sb, sb + A_STAGE, tid);

    for (int i = 0; i < nk; i++) {
        const uint32_t stA = sb + (uint32_t)(i & 1) * STAGE_BYTES;
        const uint32_t stB = stA + A_STAGE;
        if (i + 1 < nk) {
            const uint32_t nA = sb + (uint32_t)((i + 1) & 1) * STAGE_BYTES;
            g_load(A, Bt, K, mBase, nBase, i + 1, nA, nA + A_STAGE, tid);
            asm volatile("cp.async.wait_group 1;\n");
        } else {
            asm volatile("cp.async.wait_group 0;\n");
        }
        __syncthreads();

#pragma unroll
        for (int ks = 0; ks < 4; ks++) {
            unsigned a[4][4], b[4][4];
#pragma unroll
            for (int mt = 0; mt < 4; mt++)
                ldsm4(a[mt][0], a[mt][1], a[mt][2], a[mt][3],
                      stA + aFragOff + (uint32_t)(mt * 16 * GSTH * 2 + ks * 32));
#pragma unroll
            for (int p = 0; p < 4; p++)
                ldsm4(b[p][0], b[p][1], b[p][2], b[p][3],
                      stB + bFragOff + (uint32_t)(p * 16 * GSTH * 2 + ks * 32));
#pragma unroll
            for (int mt = 0; mt < 4; mt++)
#pragma unroll
                for (int nt = 0; nt < 8; nt++) {
                    const int p = nt >> 1, idx = (nt & 1) * 2;
                    mma_f16(c[mt][nt][0], c[mt][nt][1], c[mt][nt][2], c[mt][nt][3],
                            a[mt][0], a[mt][1], a[mt][2], a[mt][3],
                            b[p][idx], b[p][idx + 1]);
                }
        }
        __syncthreads();
    }

    // epilogue
#pragma unroll
    for (int mt = 0; mt < 4; mt++) {
        const int r0 = mBase + wm * 64 + mt * 16;
#pragma unroll
        for (int nt = 0; nt < 8; nt++) {
            const int c0 = nBase + wn * 64 + nt * 8 + tq * 2;
            if constexpr (sizeof(OutT) == 2) {
                *(__half2*)&C[(size_t)(r0 + g)     * N + c0] =
                    __floats2half2_rn(c[mt][nt][0], c[mt][nt][1]);
                *(__half2*)&C[(size_t)(r0 + g + 8) * N + c0] =
                    __floats2half2_rn(c[mt][nt][2], c[mt][nt][3]);
            } else {
                *(float2*)&C[(size_t)(r0 + g)     * N + c0] = make_float2(c[mt][nt][0], c[mt][nt][1]);
                *(float2*)&C[(size_t)(r0 + g + 8) * N + c0] = make_float2(c[mt][nt][2], c[mt][nt][3]);
            }
        }
    }
}

// ---------------- fused RMSNorm + RoPE (in place on half g_qkv q/k slices) ----------------
__global__ void __launch_bounds__(128) norm_rope_kernel(
    const float* __restrict__ qw, const float* __restrict__ kw)
{
    int rid = blockIdx.x;
    int tid = threadIdx.x;
    __half* buf;
    const float* w;
    int t;
    if (rid < T_TOK * NH) {
        t = rid / NH;
        int h = rid % NH;
        buf = g_qkv + (size_t)t * QKVS + (size_t)h * HD;
        w = qw;
    } else {
        rid -= T_TOK * NH;
        t = rid / NKV;
        int h = rid % NKV;
        buf = g_qkv + (size_t)t * QKVS + 4096 + (size_t)h * HD;
        w = kw;
    }
    float x = __half2float(buf[tid]);
    float s = x * x;
#pragma unroll
    for (int o = 16; o > 0; o >>= 1) s += __shfl_xor_sync(0xffffffffu, s, o);
    __shared__ float ws[4];
    __shared__ float sh[128];
    if ((tid & 31) == 0) ws[tid >> 5] = s;
    __syncthreads();
    s = ws[0] + ws[1] + ws[2] + ws[3];
    float y = x * rsqrtf(s * (1.0f / 128.0f) + 1e-6f) * w[tid];
    sh[tid] = y;
    __syncthreads();
    float c = g_cos[(size_t)t * 64 + (tid & 63)];
    float sn = g_sin[(size_t)t * 64 + (tid & 63)];
    float rot = (tid < 64) ? -sh[tid + 64] : sh[tid - 64];
    buf[tid] = __float2half_rn(y * c + rot * sn);
}

// ---------------- fp16 tensor-core flash attention (GQA-shared K/V, 2 blocks/SM) --------
// Block: 32 q-positions x 2 heads of one kv group = 64 A-rows; K-tiles of 64.
// 4 warps (128 threads), each owns 16 A-rows. 2 blocks/SM for barrier decoupling.
#define AST_H 136
#define PST_H 72
#define ATT_SMEM ((64*AST_H + 64*AST_H + 64*AST_H + 4*16*PST_H) * 2)   // 61440 B

__global__ void __launch_bounds__(128, 2) attn_f16_kernel() {
    extern __shared__ __half smh[];
    __half* Qs = smh;                        // [64][136]   rows = 2 heads x 32 q
    __half* Ks = Qs + 64 * AST_H;            // [64][136]   rows = kpos
    __half* Vs = Ks + 64 * AST_H;            // [64][136]   rows = kpos, cols = d
    __half* Pw = Vs + 64 * AST_H;            // 4 x [16][72]

    const int qt = 63 - blockIdx.x;          // large tiles first
    const int hp = blockIdx.y;               // head-pair id: kvh = hp>>1, pair = hp&1
    const int kvh = hp >> 1;
    const int headBase = kvh * 4 + (hp & 1) * 2;
    const int b = blockIdx.z;
    const int tid = threadIdx.x;
    const int warp = tid >> 5, lane = tid & 31;
    const int g = lane >> 2, tq = lane & 3;
    const float scale = 0.08838834764831845f;

    __half* Ps = Pw + warp * 16 * PST_H;
    const int rloc0 = warp * 16 + g;                 // A-row (and +8), 0..63
    const int q0 = qt * 32 + (rloc0 & 31);
    const int head = headBase + (rloc0 >> 5);

    const uint32_t qAddr = smem_u32(Qs) +
        (uint32_t)((warp * 16 + (lane & 15)) * AST_H) * 2 + ((lane & 16) ? 16u : 0u);
    const uint32_t kAddr = smem_u32(Ks) +
        (uint32_t)(((lane & 7) + ((lane & 16) >> 1)) * AST_H) * 2 + ((lane & 8) << 1);
    const uint32_t vAddr = smem_u32(Vs) +
        (uint32_t)(((lane & 7) + ((lane & 8) ? 8 : 0)) * AST_H) * 2 + ((lane & 16) ? 16u : 0u);
    const uint32_t pAddr = smem_u32(Ps) +
        (uint32_t)((lane & 15) * PST_H) * 2 + ((lane & 16) ? 16u : 0u);

    // load Q tile: row r (0..63) -> head headBase + r/32, qpos qt*32 + r%32
#pragma unroll
    for (int i = 0; i < 8; i++) {
        int e = tid + (i << 7);                  // 0..1023
        int r = e >> 4, ds = (e & 15) << 3;
        cp16s(smem_u32(&Qs[r * AST_H + ds]),
              &g_qkv[(size_t)(b * SEQ + qt * 32 + (r & 31)) * QKVS +
                     (size_t)(headBase + (r >> 5)) * HD + ds]);
    }
    asm volatile("cp.async.commit_group;\n");

    float m0 = -1e30f, m1 = -1e30f, l0 = 0.f, l1 = 0.f;
    float o[16][4];
#pragma unroll
    for (int nt = 0; nt < 16; nt++)
#pragma unroll
        for (int e = 0; e < 4; e++) o[nt][e] = 0.f;

    const int nkt = (qt * 32 + 31) / 64 + 1;
    for (int kt = 0; kt < nkt; kt++) {
        if (kt) __syncthreads();
        const int kBase = kt * 64;
#pragma unroll
        for (int i = 0; i < 8; i++) {
            int e = tid + (i << 7);              // 0..1023
            int r = e >> 4, ds = (e & 15) << 3;
            const size_t go = (size_t)(b * SEQ + kBase + r) * QKVS + (size_t)kvh * HD + ds;
            cp16s(smem_u32(&Ks[r * AST_H + ds]), &g_qkv[go + 4096]);
            cp16s(smem_u32(&Vs[r * AST_H + ds]), &g_qkv[go + 5120]);
        }
        asm volatile("cp.async.commit_group;\n");
        asm volatile("cp.async.wait_group 0;\n");
        __syncthreads();

        // ---- S = Q K^T : 16 rows x 64 kpos per warp; 8 k16 steps over d ----
        float s[8][4];
#pragma unroll
        for (int nt = 0; nt < 8; nt++)
#pragma unroll
            for (int e = 0; e < 4; e++) s[nt][e] = 0.f;

#pragma unroll
        for (int ks = 0; ks < 8; ks++) {
            unsigned qa[4];
            ldsm4(qa[0], qa[1], qa[2], qa[3], qAddr + (uint32_t)(ks * 32));
#pragma unroll
            for (int p = 0; p < 4; p++) {
                unsigned kb[4];
                ldsm4(kb[0], kb[1], kb[2], kb[3],
                      kAddr + (uint32_t)(p * 16 * AST_H * 2 + ks * 32));
                mma_f16(s[2*p][0], s[2*p][1], s[2*p][2], s[2*p][3],
                        qa[0], qa[1], qa[2], qa[3], kb[0], kb[1]);
                mma_f16(s[2*p+1][0], s[2*p+1][1], s[2*p+1][2], s[2*p+1][3],
                        qa[0], qa[1], qa[2], qa[3], kb[2], kb[3]);
            }
        }

        // ---- scale + causal mask ----
        const bool edge = (kBase + 63 > qt * 32);
#pragma unroll
        for (int nt = 0; nt < 8; nt++) {
            int c0 = kBase + nt * 8 + tq * 2;
            s[nt][0] *= scale; s[nt][1] *= scale;
            s[nt][2] *= scale; s[nt][3] *= scale;
            if (edge) {
                if (c0     > q0)     s[nt][0] = -1e30f;
                if (c0 + 1 > q0)     s[nt][1] = -1e30f;
                if (c0     > q0 + 8) s[nt][2] = -1e30f;
                if (c0 + 1 > q0 + 8) s[nt][3] = -1e30f;
            }
        }

        // ---- online softmax (rows q0, q0+8; quad reduction) ----
        float mx0 = -1e30f, mx1 = -1e30f;
#pragma unroll
        for (int nt = 0; nt < 8; nt++) {
            mx0 = fmaxf(mx0, fmaxf(s[nt][0], s[nt][1]));
            mx1 = fmaxf(mx1, fmaxf(s[nt][2], s[nt][3]));
        }
        mx0 = fmaxf(mx0, __shfl_xor_sync(0xffffffffu, mx0, 1));
        mx0 = fmaxf(mx0, __shfl_xor_sync(0xffffffffu, mx0, 2));
        mx1 = fmaxf(mx1, __shfl_xor_sync(0xffffffffu, mx1, 1));
        mx1 = fmaxf(mx1, __shfl_xor_sync(0xffffffffu, mx1, 2));

        float mn0 = fmaxf(m0, mx0), mn1 = fmaxf(m1, mx1);
        float al0 = __expf(m0 - mn0), al1 = __expf(m1 - mn1);
        m0 = mn0; m1 = mn1;

        float ps0 = 0.f, ps1 = 0.f;
#pragma unroll
        for (int nt = 0; nt < 8; nt++) {
            float p0 = __expf(s[nt][0] - mn0);
            float p1 = __expf(s[nt][1] - mn0);
            float p2 = __expf(s[nt][2] - mn1);
            float p3 = __expf(s[nt][3] - mn1);
            ps0 += p0 + p1; ps1 += p2 + p3;
            int c0 = nt * 8 + tq * 2;
            *(__half2*)&Ps[(g)     * PST_H + c0] = __floats2half2_rn(p0, p1);
            *(__half2*)&Ps[(g + 8) * PST_H + c0] = __floats2half2_rn(p2, p3);
        }
        ps0 += __shfl_xor_sync(0xffffffffu, ps0, 1);
        ps0 += __shfl_xor_sync(0xffffffffu, ps0, 2);
        ps1 += __shfl_xor_sync(0xffffffffu, ps1, 1);
        ps1 += __shfl_xor_sync(0xffffffffu, ps1, 2);
        l0 = l0 * al0 + ps0;
        l1 = l1 * al1 + ps1;

#pragma unroll
        for (int nt = 0; nt < 16; nt++) {
            o[nt][0] *= al0; o[nt][1] *= al0;
            o[nt][2] *= al1; o[nt][3] *= al1;
        }
        __syncwarp();

        // ---- O += P V : 16 rows x 128 d per warp; 4 k16 steps over kpos ----
#pragma unroll
        for (int ks = 0; ks < 4; ks++) {
            unsigned pa[4];
            ldsm4(pa[0], pa[1], pa[2], pa[3], pAddr + (uint32_t)(ks * 32));
            const uint32_t vRow = vAddr + (uint32_t)(ks * 16 * AST_H * 2);
#pragma unroll
            for (int p = 0; p < 8; p++) {
                unsigned vb[4];
                ldsm4t(vb[0], vb[1], vb[2], vb[3], vRow + (uint32_t)(p * 32));
                mma_f16(o[2*p][0], o[2*p][1], o[2*p][2], o[2*p][3],
                        pa[0], pa[1], pa[2], pa[3], vb[0], vb[1]);
                mma_f16(o[2*p+1][0], o[2*p+1][1], o[2*p+1][2], o[2*p+1][3],
                        pa[0], pa[1], pa[2], pa[3], vb[2], vb[3]);
            }
        }
    }

    // ---- epilogue (half output for final GEMM) ----
    float inv0 = 1.0f / l0, inv1 = 1.0f / l1;
    const size_t r0off = (size_t)(b * SEQ + q0) * QDIM + (size_t)head * HD;
    const size_t r1off = r0off + 8 * QDIM;
#pragma unroll
    for (int nt = 0; nt < 16; nt++) {
        int c0 = nt * 8 + tq * 2;
        *(__half2*)&g_ao[r0off + c0] = __floats2half2_rn(o[nt][0] * inv0, o[nt][1] * inv0);
        *(__half2*)&g_ao[r1off + c0] = __floats2half2_rn(o[nt][2] * inv1, o[nt][3] * inv1);
    }
}

// ---------------- launch ----------------
extern "C" void kernel_launch(void* const* d_in, const int* in_sizes, int n_in,
                              void* d_out, int out_size) {
    const float* hid = (const float*)d_in[0];
    const int*   pos = (const int*)d_in[1];
    const float* Wq  = (const float*)d_in[2];
    const float* Wk  = (const float*)d_in[3];
    const float* Wv  = (const float*)d_in[4];
    const float* Wo  = (const float*)d_in[5];
    const float* qw  = (const float*)d_in[6];
    const float* kw  = (const float*)d_in[7];
    float* out = (float*)d_out;

    __half *hid_h, *wtall, *wot, *qkv, *ao;
    cudaGetSymbolAddress((void**)&hid_h, g_hid_h);
    cudaGetSymbolAddress((void**)&wtall, g_WtAll);
    cudaGetSymbolAddress((void**)&wot, g_WoT);
    cudaGetSymbolAddress((void**)&qkv, g_qkv);
    cudaGetSymbolAddress((void**)&ao, g_ao);

    cudaFuncSetAttribute(gemm_f16_kernel<__half>, cudaFuncAttributeMaxDynamicSharedMemorySize, GEMM_SMEM);
    cudaFuncSetAttribute(gemm_f16_kernel<float>, cudaFuncAttributeMaxDynamicSharedMemorySize, GEMM_SMEM);
    cudaFuncSetAttribute(attn_f16_kernel, cudaFuncAttributeMaxDynamicSharedMemorySize, ATT_SMEM);

    // hidden -> fp16
    {
        int n4 = T_TOK * HIDN / 4;
        conv_half_kernel<<<(n4 + 255) / 256, 256>>>((const float4*)hid, (__half2*)hid_h, n4);
    }
    // all 4 weight transposes in one launch
    transpose_all_kernel<<<TRANS_BLOCKS, 256>>>(Wq, Wk, Wv, Wo);
    rope_table_kernel<<<(T_TOK * 64) / 256, 256>>>(pos);

    // fused QKV projection: [4096,2560] @ [6144,2560]^T -> half [4096,6144]
    gemm_f16_kernel<__half><<<dim3(QKVS / TN, T_TOK / TM), 128, GEMM_SMEM>>>(
        hid_h, wtall, qkv, T_TOK, QKVS, HIDN);

    norm_rope_kernel<<<T_TOK * (NH + NKV), 128>>>(qw, kw);

    // attention: 2 heads per block, 2 blocks/SM
    attn_f16_kernel<<<dim3(64, NKV * 2, BATCH), 128, ATT_SMEM>>>();

    // output projection: [4096,4096] @ [2560,4096]^T -> fp32 out [4096,2560]
    gemm_f16_kernel<float><<<dim3(HIDN / TN, T_TOK / TM), 128, GEMM_SMEM>>>(
        ao, wot, out, T_TOK, HIDN, QDIM);
}

// round 14
// speedup vs baseline: 1.0371x; 1.0371x over previous
#include <cuda_runtime.h>
#include <cuda_fp16.h>
#include <math.h>
#include <stdint.h>

// ---------------- problem constants ----------------
#define BATCH 2
#define SEQ   2048
#define T_TOK 4096
#define HIDN  2560
#define NH    32
#define NKV   8
#define HD    128
#define QDIM  4096
#define KVDIM 1024
#define QKVS  6144          // packed q|k|v row stride (halves)

// ---------------- scratch ----------------
__device__ __half g_hid_h[(size_t)T_TOK * HIDN];
__device__ __half g_WtAll[(size_t)QKVS * HIDN];   // WqT|WkT|WvT rows, each [*, 2560] K-major
__device__ __half g_WoT[(size_t)HIDN * QDIM];     // WoT [2560][4096] K-major
__device__ __half g_qkv[(size_t)T_TOK * QKVS];
__device__ __half g_ao[(size_t)T_TOK * QDIM];
__device__ float  g_cos[(size_t)T_TOK * 64];
__device__ float  g_sin[(size_t)T_TOK * 64];

// ---------------- helpers ----------------
__device__ __forceinline__ uint32_t smem_u32(const void* p) {
    uint32_t a;
    asm("{ .reg .u64 t; cvta.to.shared.u64 t, %1; cvt.u32.u64 %0, t; }" : "=r"(a) : "l"(p));
    return a;
}

__device__ __forceinline__ void cp16s(uint32_t saddr, const void* gsrc) {
    asm volatile("cp.async.cg.shared.global [%0], [%1], 16;\n" :: "r"(saddr), "l"(gsrc));
}

__device__ __forceinline__ void ldsm4(unsigned& r0, unsigned& r1, unsigned& r2, unsigned& r3,
                                      uint32_t addr) {
    asm volatile("ldmatrix.sync.aligned.m8n8.x4.shared.b16 {%0,%1,%2,%3}, [%4];"
                 : "=r"(r0), "=r"(r1), "=r"(r2), "=r"(r3) : "r"(addr));
}

__device__ __forceinline__ void ldsm4t(unsigned& r0, unsigned& r1, unsigned& r2, unsigned& r3,
                                       uint32_t addr) {
    asm volatile("ldmatrix.sync.aligned.m8n8.x4.trans.shared.b16 {%0,%1,%2,%3}, [%4];"
                 : "=r"(r0), "=r"(r1), "=r"(r2), "=r"(r3) : "r"(addr));
}

// m16n8k16 fp16 mma, fp32 accumulate
__device__ __forceinline__ void mma_f16(
    float& d0, float& d1, float& d2, float& d3,
    unsigned a0, unsigned a1, unsigned a2, unsigned a3,
    unsigned b0, unsigned b1)
{
    asm volatile(
        "mma.sync.aligned.m16n8k16.row.col.f32.f16.f16.f32 "
        "{%0,%1,%2,%3},{%4,%5,%6,%7},{%8,%9},{%0,%1,%2,%3};"
        : "+f"(d0), "+f"(d1), "+f"(d2), "+f"(d3)
        : "r"(a0), "r"(a1), "r"(a2), "r"(a3), "r"(b0), "r"(b1));
}

// ---------------- fp32 -> fp16 conversion ----------------
__global__ void conv_half_kernel(const float4* __restrict__ in, __half2* __restrict__ out, int n4) {
    int i = blockIdx.x * blockDim.x + threadIdx.x;
    int stride = gridDim.x * blockDim.x;
    for (; i < n4; i += stride) {
        float4 v = in[i];
        out[2 * i]     = __floats2half2_rn(v.x, v.y);
        out[2 * i + 1] = __floats2half2_rn(v.z, v.w);
    }
}

// ---------------- combined weight transpose + fp16 (all 4 weights, one launch) ----------
#define TRANS_BLOCKS 25600
__global__ void __launch_bounds__(256) transpose_all_kernel(
    const float* __restrict__ Wq, const float* __restrict__ Wk,
    const float* __restrict__ Wv, const float* __restrict__ Wo)
{
    int bid = blockIdx.x;
    const float* in;
    __half* out;
    int R, C;
    if (bid < 10240)      { in = Wq; out = g_WtAll;                         R = HIDN; C = QDIM;  }
    else if (bid < 12800) { in = Wk; out = g_WtAll + (size_t)4096 * HIDN;   R = HIDN; C = KVDIM; bid -= 10240; }
    else if (bid < 15360) { in = Wv; out = g_WtAll + (size_t)5120 * HIDN;   R = HIDN; C = KVDIM; bid -= 12800; }
    else                  { in = Wo; out = g_WoT;                           R = QDIM; C = HIDN;  bid -= 15360; }
    const int nbx = C / 32;
    const int bc = (bid % nbx) * 32, br = (bid / nbx) * 32;

    __shared__ float t[32][33];
    const int tx = threadIdx.x & 31, ty = threadIdx.x >> 5;   // 32 x 8
#pragma unroll
    for (int i = 0; i < 32; i += 8)
        t[ty + i][tx] = in[(size_t)(br + ty + i) * C + bc + tx];
    __syncthreads();
#pragma unroll
    for (int i = 0; i < 32; i += 8)
        out[(size_t)(bc + ty + i) * R + br + tx] = __float2half_rn(t[tx][ty + i]);
}

// ---------------- RoPE cos/sin table ----------------
__global__ void rope_table_kernel(const int* __restrict__ p32) {
    int idx = blockIdx.x * blockDim.x + threadIdx.x;
    if (idx >= T_TOK * 64) return;
    int t = idx >> 6;
    int i = idx & 63;
    bool is64 = (p32[1] == 0 && p32[2] == 1);
    int pos = is64 ? p32[2 * t] : p32[t];
    double ang = (double)pos * exp(-(double)i * (log(1000000.0) / 64.0));
    g_cos[idx] = (float)cos(ang);
    g_sin[idx] = (float)sin(ang);
}

// ---------------- fp16 mma GEMM: C[M,N] = A[M,K] @ Bt[N,K]^T ----------------
// 128-thread blocks, 2 blocks/SM (barrier decoupling). Block tile 128x128,
// 4 warps (2x2), warp tile 64x64, K-chunk 64.
// 3-stage cp.async pipeline, prefetch depth 2, ONE __syncthreads per chunk.
#define TM 128
#define TN 128
#define GSTH 72
#define A_STAGE (TM * GSTH * 2)                 // 18432 B
#define STAGE_BYTES ((TM + TN) * GSTH * 2)      // 36864 B
#define GEMM_SMEM (3 * STAGE_BYTES)             // 110592 B -> still 2 blocks/SM

__device__ __forceinline__ void g_load(
    const __half* __restrict__ A, const __half* __restrict__ Bt, int K,
    int mBase, int nBase, int kc, uint32_t stage, int tid)
{
    const uint32_t sA = stage, sB = stage + A_STAGE;
    const __half* Ag = A + (size_t)mBase * K + (size_t)kc * 64;
#pragma unroll
    for (int i = 0; i < 8; i++) {
        int e = tid + i * 128;               // 128 rows x 8 chunks
        int r = e >> 3, q = (e & 7) << 3;    // q in halves
        cp16s(sA + (uint32_t)(r * GSTH + q) * 2, Ag + (size_t)r * K + q);
    }
    const __half* Bg = Bt + (size_t)nBase * K + (size_t)kc * 64;
#pragma unroll
    for (int i = 0; i < 8; i++) {
        int e = tid + i * 128;
        int r = e >> 3, q = (e & 7) << 3;
        cp16s(sB + (uint32_t)(r * GSTH + q) * 2, Bg + (size_t)r * K + q);
    }
    asm volatile("cp.async.commit_group;\n");
}

template <typename OutT>
__global__ void __launch_bounds__(128, 2) gemm_f16_kernel(
    const __half* __restrict__ A, const __half* __restrict__ Bt, OutT* __restrict__ C,
    int M, int N, int K)
{
    extern __shared__ char smem[];
    const uint32_t sb = smem_u32(smem);
    const int tid = threadIdx.x, warp = tid >> 5, lane = tid & 31;
    const int wm = warp >> 1, wn = warp & 1;       // 2 x 2 warp grid
    const int g = lane >> 2, tq = lane & 3;
    const int mBase = blockIdx.y * TM, nBase = blockIdx.x * TN;

    float c[4][8][4];
#pragma unroll
    for (int mt = 0; mt < 4; mt++)
#pragma unroll
        for (int nt = 0; nt < 8; nt++)
#pragma unroll
            for (int e = 0; e < 4; e++) c[mt][nt][e] = 0.f;

    const uint32_t aFragOff =
        (uint32_t)((wm * 64 + (lane & 15)) * GSTH) * 2 + ((lane & 16) ? 16u : 0u);
    const uint32_t bFragOff =
        (uint32_t)((wn * 64 + (lane & 7) + ((lane & 16) >> 1)) * GSTH) * 2 + ((lane & 8) << 1);

    const int nk = K >> 6;   // 40 or 64 here, always >= 2
    g_load(A, Bt, K, mBase, nBase, 0, sb, tid);
    g_load(A, Bt, K, mBase, nBase, 1, sb + STAGE_BYTES, tid);

    uint32_t stage = 0;      // byte offset of current stage within smem
    for (int i = 0; i < nk; i++) {
        if (i + 1 < nk) {
            asm volatile("cp.async.wait_group 1;\n");
        } else {
            asm volatile("cp.async.wait_group 0;\n");
        }
        __syncthreads();     // single barrier per chunk: protects stage i (ready)
                             // and stage (i+2)%3 (all readers of iter i-1 done)
        if (i + 2 < nk) {
            uint32_t nxt = stage + 2 * STAGE_BYTES;
            if (nxt >= 3 * STAGE_BYTES) nxt -= 3 * STAGE_BYTES;
            g_load(A, Bt, K, mBase, nBase, i + 2, sb + nxt, tid);
        }

        const uint32_t stA = sb + stage;
        const uint32_t stB = stA + A_STAGE;
#pragma unroll
        for (int ks = 0; ks < 4; ks++) {
            unsigned a[4][4], b[4][4];
#pragma unroll
            for (int mt = 0; mt < 4; mt++)
                ldsm4(a[mt][0], a[mt][1], a[mt][2], a[mt][3],
                      stA + aFragOff + (uint32_t)(mt * 16 * GSTH * 2 + ks * 32));
#pragma unroll
            for (int p = 0; p < 4; p++)
                ldsm4(b[p][0], b[p][1], b[p][2], b[p][3],
                      stB + bFragOff + (uint32_t)(p * 16 * GSTH * 2 + ks * 32));
#pragma unroll
            for (int mt = 0; mt < 4; mt++)
#pragma unroll
                for (int nt = 0; nt < 8; nt++) {
                    const int p = nt >> 1, idx = (nt & 1) * 2;
                    mma_f16(c[mt][nt][0], c[mt][nt][1], c[mt][nt][2], c[mt][nt][3],
                            a[mt][0], a[mt][1], a[mt][2], a[mt][3],
                            b[p][idx], b[p][idx + 1]);
                }
        }
        stage += STAGE_BYTES;
        if (stage >= 3 * STAGE_BYTES) stage = 0;
    }

    // epilogue
#pragma unroll
    for (int mt = 0; mt < 4; mt++) {
        const int r0 = mBase + wm * 64 + mt * 16;
#pragma unroll
        for (int nt = 0; nt < 8; nt++) {
            const int c0 = nBase + wn * 64 + nt * 8 + tq * 2;
            if constexpr (sizeof(OutT) == 2) {
                *(__half2*)&C[(size_t)(r0 + g)     * N + c0] =
                    __floats2half2_rn(c[mt][nt][0], c[mt][nt][1]);
                *(__half2*)&C[(size_t)(r0 + g + 8) * N + c0] =
                    __floats2half2_rn(c[mt][nt][2], c[mt][nt][3]);
            } else {
                *(float2*)&C[(size_t)(r0 + g)     * N + c0] = make_float2(c[mt][nt][0], c[mt][nt][1]);
                *(float2*)&C[(size_t)(r0 + g + 8) * N + c0] = make_float2(c[mt][nt][2], c[mt][nt][3]);
            }
        }
    }
}

// ---------------- fused RMSNorm + RoPE (in place on half g_qkv q/k slices) ----------------
__global__ void __launch_bounds__(128) norm_rope_kernel(
    const float* __restrict__ qw, const float* __restrict__ kw)
{
    int rid = blockIdx.x;
    int tid = threadIdx.x;
    __half* buf;
    const float* w;
    int t;
    if (rid < T_TOK * NH) {
        t = rid / NH;
        int h = rid % NH;
        buf = g_qkv + (size_t)t * QKVS + (size_t)h * HD;
        w = qw;
    } else {
        rid -= T_TOK * NH;
        t = rid / NKV;
        int h = rid % NKV;
        buf = g_qkv + (size_t)t * QKVS + 4096 + (size_t)h * HD;
        w = kw;
    }
    float x = __half2float(buf[tid]);
    float s = x * x;
#pragma unroll
    for (int o = 16; o > 0; o >>= 1) s += __shfl_xor_sync(0xffffffffu, s, o);
    __shared__ float ws[4];
    __shared__ float sh[128];
    if ((tid & 31) == 0) ws[tid >> 5] = s;
    __syncthreads();
    s = ws[0] + ws[1] + ws[2] + ws[3];
    float y = x * rsqrtf(s * (1.0f / 128.0f) + 1e-6f) * w[tid];
    sh[tid] = y;
    __syncthreads();
    float c = g_cos[(size_t)t * 64 + (tid & 63)];
    float sn = g_sin[(size_t)t * 64 + (tid & 63)];
    float rot = (tid < 64) ? -sh[tid + 64] : sh[tid - 64];
    buf[tid] = __float2half_rn(y * c + rot * sn);
}

// ---------------- fp16 tensor-core flash attention ----------------
// 128-thread blocks, 2 blocks/SM. Block: 32 q x 2 heads = 64 A-rows; K-tiles 64.
// Double-buffered K/V: prefetch tile kt+1 before computing kt; ONE sync per iter.
#define AST_H 136
#define PST_H 72
#define KV_STAGE (64 * AST_H)    // halves per K (or V) stage
#define ATT_SMEM ((64*AST_H + 4*KV_STAGE + 4*16*PST_H) * 2)   // 96256 B -> 2 blocks/SM

__global__ void __launch_bounds__(128, 2) attn_f16_kernel() {
    extern __shared__ __half smh[];
    __half* Qs = smh;                        // [64][136]   rows = 2 heads x 32 q
    __half* Ks = Qs + 64 * AST_H;            // [2][64][136]
    __half* Vs = Ks + 2 * KV_STAGE;          // [2][64][136]
    __half* Pw = Vs + 2 * KV_STAGE;          // 4 x [16][72]

    const int qt = 63 - blockIdx.x;          // large tiles first
    const int hp = blockIdx.y;               // head-pair id
    const int kvh = hp >> 1;
    const int headBase = kvh * 4 + (hp & 1) * 2;
    const int b = blockIdx.z;
    const int tid = threadIdx.x;
    const int warp = tid >> 5, lane = tid & 31;
    const int g = lane >> 2, tq = lane & 3;
    const float scale = 0.08838834764831845f;

    __half* Ps = Pw + warp * 16 * PST_H;
    const int rloc0 = warp * 16 + g;                 // A-row (and +8), 0..63
    const int q0 = qt * 32 + (rloc0 & 31);
    const int head = headBase + (rloc0 >> 5);

    const uint32_t qAddr = smem_u32(Qs) +
        (uint32_t)((warp * 16 + (lane & 15)) * AST_H) * 2 + ((lane & 16) ? 16u : 0u);
    const uint32_t kAddr0 = smem_u32(Ks) +
        (uint32_t)(((lane & 7) + ((lane & 16) >> 1)) * AST_H) * 2 + ((lane & 8) << 1);
    const uint32_t vAddr0 = smem_u32(Vs) +
        (uint32_t)(((lane & 7) + ((lane & 8) ? 8 : 0)) * AST_H) * 2 + ((lane & 16) ? 16u : 0u);
    const uint32_t pAddr = smem_u32(Ps) +
        (uint32_t)((lane & 15) * PST_H) * 2 + ((lane & 16) ? 16u : 0u);

    // ---- prologue: Q tile, then KV tile 0 ----
#pragma unroll
    for (int i = 0; i < 8; i++) {
        int e = tid + (i << 7);                  // 0..1023
        int r = e >> 4, ds = (e & 15) << 3;
        cp16s(smem_u32(&Qs[r * AST_H + ds]),
              &g_qkv[(size_t)(b * SEQ + qt * 32 + (r & 31)) * QKVS +
                     (size_t)(headBase + (r >> 5)) * HD + ds]);
    }
    asm volatile("cp.async.commit_group;\n");

    const int nkt = (qt * 32 + 31) / 64 + 1;

#pragma unroll
    for (int i = 0; i < 8; i++) {
        int e = tid + (i << 7);
        int r = e >> 4, ds = (e & 15) << 3;
        const size_t go = (size_t)(b * SEQ + r) * QKVS + (size_t)kvh * HD + ds;
        cp16s(smem_u32(&Ks[r * AST_H + ds]), &g_qkv[go + 4096]);
        cp16s(smem_u32(&Vs[r * AST_H + ds]), &g_qkv[go + 5120]);
    }
    asm volatile("cp.async.commit_group;\n");
    asm volatile("cp.async.wait_group 0;\n");
    __syncthreads();

    float m0 = -1e30f, m1 = -1e30f, l0 = 0.f, l1 = 0.f;
    float o[16][4];
#pragma unroll
    for (int nt = 0; nt < 16; nt++)
#pragma unroll
        for (int e = 0; e < 4; e++) o[nt][e] = 0.f;

    for (int kt = 0; kt < nkt; kt++) {
        // prefetch next KV tile into the other stage (safe: last reads of that
        // stage finished before the sync that ended iteration kt-1)
        if (kt + 1 < nkt) {
            const int nBase = (kt + 1) * 64;
            const uint32_t so = (uint32_t)(((kt + 1) & 1) * KV_STAGE) * 2;
#pragma unroll
            for (int i = 0; i < 8; i++) {
                int e = tid + (i << 7);
                int r = e >> 4, ds = (e & 15) << 3;
                const size_t go = (size_t)(b * SEQ + nBase + r) * QKVS + (size_t)kvh * HD + ds;
                cp16s(smem_u32(&Ks[r * AST_H + ds]) + so, &g_qkv[go + 4096]);
                cp16s(smem_u32(&Vs[r * AST_H + ds]) + so, &g_qkv[go + 5120]);
            }
            asm volatile("cp.async.commit_group;\n");
        }

        const int kBase = kt * 64;
        const uint32_t so = (uint32_t)((kt & 1) * KV_STAGE) * 2;
        const uint32_t kAddr = kAddr0 + so;
        const uint32_t vAddr = vAddr0 + so;

        // ---- S = Q K^T : 16 rows x 64 kpos per warp; 8 k16 steps over d ----
        float s[8][4];
#pragma unroll
        for (int nt = 0; nt < 8; nt++)
#pragma unroll
            for (int e = 0; e < 4; e++) s[nt][e] = 0.f;

#pragma unroll
        for (int ks = 0; ks < 8; ks++) {
            unsigned qa[4];
            ldsm4(qa[0], qa[1], qa[2], qa[3], qAddr + (uint32_t)(ks * 32));
#pragma unroll
            for (int p = 0; p < 4; p++) {
                unsigned kb[4];
                ldsm4(kb[0], kb[1], kb[2], kb[3],
                      kAddr + (uint32_t)(p * 16 * AST_H * 2 + ks * 32));
                mma_f16(s[2*p][0], s[2*p][1], s[2*p][2], s[2*p][3],
                        qa[0], qa[1], qa[2], qa[3], kb[0], kb[1]);
                mma_f16(s[2*p+1][0], s[2*p+1][1], s[2*p+1][2], s[2*p+1][3],
                        qa[0], qa[1], qa[2], qa[3], kb[2], kb[3]);
            }
        }

        // ---- scale + causal mask ----
        const bool edge = (kBase + 63 > qt * 32);
#pragma unroll
        for (int nt = 0; nt < 8; nt++) {
            int c0 = kBase + nt * 8 + tq * 2;
            s[nt][0] *= scale; s[nt][1] *= scale;
            s[nt][2] *= scale; s[nt][3] *= scale;
            if (edge) {
                if (c0     > q0)     s[nt][0] = -1e30f;
                if (c0 + 1 > q0)     s[nt][1] = -1e30f;
                if (c0     > q0 + 8) s[nt][2] = -1e30f;
                if (c0 + 1 > q0 + 8) s[nt][3] = -1e30f;
            }
        }

        // ---- online softmax (rows q0, q0+8; quad reduction) ----
        float mx0 = -1e30f, mx1 = -1e30f;
#pragma unroll
        for (int nt = 0; nt < 8; nt++) {
            mx0 = fmaxf(mx0, fmaxf(s[nt][0], s[nt][1]));
            mx1 = fmaxf(mx1, fmaxf(s[nt][2], s[nt][3]));
        }
        mx0 = fmaxf(mx0, __shfl_xor_sync(0xffffffffu, mx0, 1));
        mx0 = fmaxf(mx0, __shfl_xor_sync(0xffffffffu, mx0, 2));
        mx1 = fmaxf(mx1, __shfl_xor_sync(0xffffffffu, mx1, 1));
        mx1 = fmaxf(mx1, __shfl_xor_sync(0xffffffffu, mx1, 2));

        float mn0 = fmaxf(m0, mx0), mn1 = fmaxf(m1, mx1);
        float al0 = __expf(m0 - mn0), al1 = __expf(m1 - mn1);
        m0 = mn0; m1 = mn1;

        float ps0 = 0.f, ps1 = 0.f;
#pragma unroll
        for (int nt = 0; nt < 8; nt++) {
            float p0 = __expf(s[nt][0] - mn0);
            float p1 = __expf(s[nt][1] - mn0);
            float p2 = __expf(s[nt][2] - mn1);
            float p3 = __expf(s[nt][3] - mn1);
            ps0 += p0 + p1; ps1 += p2 + p3;
            int c0 = nt * 8 + tq * 2;
            *(__half2*)&Ps[(g)     * PST_H + c0] = __floats2half2_rn(p0, p1);
            *(__half2*)&Ps[(g + 8) * PST_H + c0] = __floats2half2_rn(p2, p3);
        }
        ps0 += __shfl_xor_sync(0xffffffffu, ps0, 1);
        ps0 += __shfl_xor_sync(0xffffffffu, ps0, 2);
        ps1 += __shfl_xor_sync(0xffffffffu, ps1, 1);
        ps1 += __shfl_xor_sync(0xffffffffu, ps1, 2);
        l0 = l0 * al0 + ps0;
        l1 = l1 * al1 + ps1;

#pragma unroll
        for (int nt = 0; nt < 16; nt++) {
            o[nt][0] *= al0; o[nt][1] *= al0;
            o[nt][2] *= al1; o[nt][3] *= al1;
        }
        __syncwarp();

        // ---- O += P V : 16 rows x 128 d per warp; 4 k16 steps over kpos ----
#pragma unroll
        for (int ks = 0; ks < 4; ks++) {
            unsigned pa[4];
            ldsm4(pa[0], pa[1], pa[2], pa[3], pAddr + (uint32_t)(ks * 32));
            const uint32_t vRow = vAddr + (uint32_t)(ks * 16 * AST_H * 2);
#pragma unroll
            for (int p = 0; p < 8; p++) {
                unsigned vb[4];
                ldsm4t(vb[0], vb[1], vb[2], vb[3], vRow + (uint32_t)(p * 32));
                mma_f16(o[2*p][0], o[2*p][1], o[2*p][2], o[2*p][3],
                        pa[0], pa[1], pa[2], pa[3], vb[0], vb[1]);
                mma_f16(o[2*p+1][0], o[2*p+1][1], o[2*p+1][2], o[2*p+1][3],
                        pa[0], pa[1], pa[2], pa[3], vb[2], vb[3]);
            }
        }

        if (kt + 1 < nkt) {
            asm volatile("cp.async.wait_group 0;\n");   // prefetch had a full iter to land
            __syncthreads();
        }
    }

    // ---- epilogue (half output for final GEMM) ----
    float inv0 = 1.0f / l0, inv1 = 1.0f / l1;
    const size_t r0off = (size_t)(b * SEQ + q0) * QDIM + (size_t)head * HD;
    const size_t r1off = r0off + 8 * QDIM;
#pragma unroll
    for (int nt = 0; nt < 16; nt++) {
        int c0 = nt * 8 + tq * 2;
        *(__half2*)&g_ao[r0off + c0] = __floats2half2_rn(o[nt][0] * inv0, o[nt][1] * inv0);
        *(__half2*)&g_ao[r1off + c0] = __floats2half2_rn(o[nt][2] * inv1, o[nt][3] * inv1);
    }
}

// ---------------- launch ----------------
extern "C" void kernel_launch(void* const* d_in, const int* in_sizes, int n_in,
                              void* d_out, int out_size) {
    const float* hid = (const float*)d_in[0];
    const int*   pos = (const int*)d_in[1];
    const float* Wq  = (const float*)d_in[2];
    const float* Wk  = (const float*)d_in[3];
    const float* Wv  = (const float*)d_in[4];
    const float* Wo  = (const float*)d_in[5];
    const float* qw  = (const float*)d_in[6];
    const float* kw  = (const float*)d_in[7];
    float* out = (float*)d_out;

    __half *hid_h, *wtall, *wot, *qkv, *ao;
    cudaGetSymbolAddress((void**)&hid_h, g_hid_h);
    cudaGetSymbolAddress((void**)&wtall, g_WtAll);
    cudaGetSymbolAddress((void**)&wot, g_WoT);
    cudaGetSymbolAddress((void**)&qkv, g_qkv);
    cudaGetSymbolAddress((void**)&ao, g_ao);

    cudaFuncSetAttribute(gemm_f16_kernel<__half>, cudaFuncAttributeMaxDynamicSharedMemorySize, GEMM_SMEM);
    cudaFuncSetAttribute(gemm_f16_kernel<float>, cudaFuncAttributeMaxDynamicSharedMemorySize, GEMM_SMEM);
    cudaFuncSetAttribute(attn_f16_kernel, cudaFuncAttributeMaxDynamicSharedMemorySize, ATT_SMEM);

    // hidden -> fp16
    {
        int n4 = T_TOK * HIDN / 4;
        conv_half_kernel<<<(n4 + 255) / 256, 256>>>((const float4*)hid, (__half2*)hid_h, n4);
    }
    // all 4 weight transposes in one launch
    transpose_all_kernel<<<TRANS_BLOCKS, 256>>>(Wq, Wk, Wv, Wo);
    rope_table_kernel<<<(T_TOK * 64) / 256, 256>>>(pos);

    // fused QKV projection: [4096,2560] @ [6144,2560]^T -> half [4096,6144]
    gemm_f16_kernel<__half><<<dim3(QKVS / TN, T_TOK / TM), 128, GEMM_SMEM>>>(
        hid_h, wtall, qkv, T_TOK, QKVS, HIDN);

    norm_rope_kernel<<<T_TOK * (NH + NKV), 128>>>(qw, kw);

    // attention: 2 heads per block, 2 blocks/SM, double-buffered K/V
    attn_f16_kernel<<<dim3(64, NKV * 2, BATCH), 128, ATT_SMEM>>>();

    // output projection: [4096,4096] @ [2560,4096]^T -> fp32 out [4096,2560]
    gemm_f16_kernel<float><<<dim3(HIDN / TN, T_TOK / TM), 128, GEMM_SMEM>>>(
        ao, wot, out, T_TOK, HIDN, QDIM);
}

// round 15
// speedup vs baseline: 1.0377x; 1.0006x over previous
#include <cuda_runtime.h>
#include <cuda_fp16.h>
#include <math.h>
#include <stdint.h>

// ---------------- problem constants ----------------
#define BATCH 2
#define SEQ   2048
#define T_TOK 4096
#define HIDN  2560
#define NH    32
#define NKV   8
#define HD    128
#define QDIM  4096
#define KVDIM 1024
#define QKVS  6144          // packed q|k|v row stride (halves)

// ---------------- scratch ----------------
__device__ __half g_hid_h[(size_t)T_TOK * HIDN];
__device__ __half g_WtAll[(size_t)QKVS * HIDN];   // WqT|WkT|WvT rows, each [*, 2560] K-major
__device__ __half g_WoT[(size_t)HIDN * QDIM];     // WoT [2560][4096] K-major
__device__ __half g_qkv[(size_t)T_TOK * QKVS];
__device__ __half g_ao[(size_t)T_TOK * QDIM];
__device__ float  g_cos[(size_t)T_TOK * 64];
__device__ float  g_sin[(size_t)T_TOK * 64];

// ---------------- helpers ----------------
__device__ __forceinline__ uint32_t smem_u32(const void* p) {
    uint32_t a;
    asm("{ .reg .u64 t; cvta.to.shared.u64 t, %1; cvt.u32.u64 %0, t; }" : "=r"(a) : "l"(p));
    return a;
}

__device__ __forceinline__ void cp16s(uint32_t saddr, const void* gsrc) {
    asm volatile("cp.async.cg.shared.global [%0], [%1], 16;\n" :: "r"(saddr), "l"(gsrc));
}

__device__ __forceinline__ void ldsm4(unsigned& r0, unsigned& r1, unsigned& r2, unsigned& r3,
                                      uint32_t addr) {
    asm volatile("ldmatrix.sync.aligned.m8n8.x4.shared.b16 {%0,%1,%2,%3}, [%4];"
                 : "=r"(r0), "=r"(r1), "=r"(r2), "=r"(r3) : "r"(addr));
}

__device__ __forceinline__ void ldsm4t(unsigned& r0, unsigned& r1, unsigned& r2, unsigned& r3,
                                       uint32_t addr) {
    asm volatile("ldmatrix.sync.aligned.m8n8.x4.trans.shared.b16 {%0,%1,%2,%3}, [%4];"
                 : "=r"(r0), "=r"(r1), "=r"(r2), "=r"(r3) : "r"(addr));
}

// m16n8k16 fp16 mma, fp32 accumulate
__device__ __forceinline__ void mma_f16(
    float& d0, float& d1, float& d2, float& d3,
    unsigned a0, unsigned a1, unsigned a2, unsigned a3,
    unsigned b0, unsigned b1)
{
    asm volatile(
        "mma.sync.aligned.m16n8k16.row.col.f32.f16.f16.f32 "
        "{%0,%1,%2,%3},{%4,%5,%6,%7},{%8,%9},{%0,%1,%2,%3};"
        : "+f"(d0), "+f"(d1), "+f"(d2), "+f"(d3)
        : "r"(a0), "r"(a1), "r"(a2), "r"(a3), "r"(b0), "r"(b1));
}

// ---------------- fp32 -> fp16 conversion ----------------
__global__ void conv_half_kernel(const float4* __restrict__ in, __half2* __restrict__ out, int n4) {
    int i = blockIdx.x * blockDim.x + threadIdx.x;
    int stride = gridDim.x * blockDim.x;
    for (; i < n4; i += stride) {
        float4 v = in[i];
        out[2 * i]     = __floats2half2_rn(v.x, v.y);
        out[2 * i + 1] = __floats2half2_rn(v.z, v.w);
    }
}

// ---------------- combined weight transpose + fp16 (all 4 weights, one launch) ----------
#define TRANS_BLOCKS 25600
__global__ void __launch_bounds__(256) transpose_all_kernel(
    const float* __restrict__ Wq, const float* __restrict__ Wk,
    const float* __restrict__ Wv, const float* __restrict__ Wo)
{
    int bid = blockIdx.x;
    const float* in;
    __half* out;
    int R, C;
    if (bid < 10240)      { in = Wq; out = g_WtAll;                         R = HIDN; C = QDIM;  }
    else if (bid < 12800) { in = Wk; out = g_WtAll + (size_t)4096 * HIDN;   R = HIDN; C = KVDIM; bid -= 10240; }
    else if (bid < 15360) { in = Wv; out = g_WtAll + (size_t)5120 * HIDN;   R = HIDN; C = KVDIM; bid -= 12800; }
    else                  { in = Wo; out = g_WoT;                           R = QDIM; C = HIDN;  bid -= 15360; }
    const int nbx = C / 32;
    const int bc = (bid % nbx) * 32, br = (bid / nbx) * 32;

    __shared__ float t[32][33];
    const int tx = threadIdx.x & 31, ty = threadIdx.x >> 5;   // 32 x 8
#pragma unroll
    for (int i = 0; i < 32; i += 8)
        t[ty + i][tx] = in[(size_t)(br + ty + i) * C + bc + tx];
    __syncthreads();
#pragma unroll
    for (int i = 0; i < 32; i += 8)
        out[(size_t)(bc + ty + i) * R + br + tx] = __float2half_rn(t[tx][ty + i]);
}

// ---------------- RoPE cos/sin table ----------------
__global__ void rope_table_kernel(const int* __restrict__ p32) {
    int idx = blockIdx.x * blockDim.x + threadIdx.x;
    if (idx >= T_TOK * 64) return;
    int t = idx >> 6;
    int i = idx & 63;
    bool is64 = (p32[1] == 0 && p32[2] == 1);
    int pos = is64 ? p32[2 * t] : p32[t];
    double ang = (double)pos * exp(-(double)i * (log(1000000.0) / 64.0));
    g_cos[idx] = (float)cos(ang);
    g_sin[idx] = (float)sin(ang);
}

// ---------------- fp16 mma GEMM: C[M,N] = A[M,K] @ Bt[N,K]^T ----------------
// 128-thread blocks, 2 blocks/SM. Block tile 128x128, 4 warps (2x2), warp tile
// 64x64, K-chunk 64. 3-stage cp.async pipeline + register-level fragment
// pipelining (A double-buffered across ks steps, B across p groups).
#define TM 128
#define TN 128
#define GSTH 72
#define A_STAGE (TM * GSTH * 2)                 // 18432 B
#define STAGE_BYTES ((TM + TN) * GSTH * 2)      // 36864 B
#define GEMM_SMEM (3 * STAGE_BYTES)             // 110592 B -> 2 blocks/SM

__device__ __forceinline__ void g_load(
    const __half* __restrict__ A, const __half* __restrict__ Bt, int K,
    int mBase, int nBase, int kc, uint32_t stage, int tid)
{
    const uint32_t sA = stage, sB = stage + A_STAGE;
    const __half* Ag = A + (size_t)mBase * K + (size_t)kc * 64;
#pragma unroll
    for (int i = 0; i < 8; i++) {
        int e = tid + i * 128;
        int r = e >> 3, q = (e & 7) << 3;
        cp16s(sA + (uint32_t)(r * GSTH + q) * 2, Ag + (size_t)r * K + q);
    }
    const __half* Bg = Bt + (size_t)nBase * K + (size_t)kc * 64;
#pragma unroll
    for (int i = 0; i < 8; i++) {
        int e = tid + i * 128;
        int r = e >> 3, q = (e & 7) << 3;
        cp16s(sB + (uint32_t)(r * GSTH + q) * 2, Bg + (size_t)r * K + q);
    }
    asm volatile("cp.async.commit_group;\n");
}

template <typename OutT>
__global__ void __launch_bounds__(128, 2) gemm_f16_kernel(
    const __half* __restrict__ A, const __half* __restrict__ Bt, OutT* __restrict__ C,
    int M, int N, int K)
{
    extern __shared__ char smem[];
    const uint32_t sb = smem_u32(smem);
    const int tid = threadIdx.x, warp = tid >> 5, lane = tid & 31;
    const int wm = warp >> 1, wn = warp & 1;
    const int g = lane >> 2, tq = lane & 3;
    const int mBase = blockIdx.y * TM, nBase = blockIdx.x * TN;

    float c[4][8][4];
#pragma unroll
    for (int mt = 0; mt < 4; mt++)
#pragma unroll
        for (int nt = 0; nt < 8; nt++)
#pragma unroll
            for (int e = 0; e < 4; e++) c[mt][nt][e] = 0.f;

    const uint32_t aFragOff =
        (uint32_t)((wm * 64 + (lane & 15)) * GSTH) * 2 + ((lane & 16) ? 16u : 0u);
    const uint32_t bFragOff =
        (uint32_t)((wn * 64 + (lane & 7) + ((lane & 16) >> 1)) * GSTH) * 2 + ((lane & 8) << 1);

    const int nk = K >> 6;
    g_load(A, Bt, K, mBase, nBase, 0, sb, tid);
    g_load(A, Bt, K, mBase, nBase, 1, sb + STAGE_BYTES, tid);

    uint32_t stage = 0;
    for (int i = 0; i < nk; i++) {
        if (i + 1 < nk) {
            asm volatile("cp.async.wait_group 1;\n");
        } else {
            asm volatile("cp.async.wait_group 0;\n");
        }
        __syncthreads();
        if (i + 2 < nk) {
            uint32_t nxt = stage + 2 * STAGE_BYTES;
            if (nxt >= 3 * STAGE_BYTES) nxt -= 3 * STAGE_BYTES;
            g_load(A, Bt, K, mBase, nBase, i + 2, sb + nxt, tid);
        }

        const uint32_t stA = sb + stage;
        const uint32_t stB = stA + A_STAGE;

        // register-pipelined fragment schedule
        unsigned a[2][4][4];
#pragma unroll
        for (int mt = 0; mt < 4; mt++)
            ldsm4(a[0][mt][0], a[0][mt][1], a[0][mt][2], a[0][mt][3],
                  stA + aFragOff + (uint32_t)(mt * 16 * GSTH * 2));
#pragma unroll
        for (int ks = 0; ks < 4; ks++) {
            const int cq = ks & 1;
            unsigned b[2][4];
            ldsm4(b[0][0], b[0][1], b[0][2], b[0][3],
                  stB + bFragOff + (uint32_t)(ks * 32));
#pragma unroll
            for (int p = 0; p < 4; p++) {
                const int bb = p & 1;
                if (p < 3) {
                    ldsm4(b[bb ^ 1][0], b[bb ^ 1][1], b[bb ^ 1][2], b[bb ^ 1][3],
                          stB + bFragOff + (uint32_t)((p + 1) * 16 * GSTH * 2 + ks * 32));
                } else if (ks < 3) {
#pragma unroll
                    for (int mt = 0; mt < 4; mt++)
                        ldsm4(a[cq ^ 1][mt][0], a[cq ^ 1][mt][1],
                              a[cq ^ 1][mt][2], a[cq ^ 1][mt][3],
                              stA + aFragOff + (uint32_t)(mt * 16 * GSTH * 2 + (ks + 1) * 32));
                }
#pragma unroll
                for (int mt = 0; mt < 4; mt++) {
                    mma_f16(c[mt][2*p][0], c[mt][2*p][1], c[mt][2*p][2], c[mt][2*p][3],
                            a[cq][mt][0], a[cq][mt][1], a[cq][mt][2], a[cq][mt][3],
                            b[bb][0], b[bb][1]);
                    mma_f16(c[mt][2*p+1][0], c[mt][2*p+1][1], c[mt][2*p+1][2], c[mt][2*p+1][3],
                            a[cq][mt][0], a[cq][mt][1], a[cq][mt][2], a[cq][mt][3],
                            b[bb][2], b[bb][3]);
                }
            }
        }
        stage += STAGE_BYTES;
        if (stage >= 3 * STAGE_BYTES) stage = 0;
    }

    // epilogue
#pragma unroll
    for (int mt = 0; mt < 4; mt++) {
        const int r0 = mBase + wm * 64 + mt * 16;
#pragma unroll
        for (int nt = 0; nt < 8; nt++) {
            const int c0 = nBase + wn * 64 + nt * 8 + tq * 2;
            if constexpr (sizeof(OutT) == 2) {
                *(__half2*)&C[(size_t)(r0 + g)     * N + c0] =
                    __floats2half2_rn(c[mt][nt][0], c[mt][nt][1]);
                *(__half2*)&C[(size_t)(r0 + g + 8) * N + c0] =
                    __floats2half2_rn(c[mt][nt][2], c[mt][nt][3]);
            } else {
                *(float2*)&C[(size_t)(r0 + g)     * N + c0] = make_float2(c[mt][nt][0], c[mt][nt][1]);
                *(float2*)&C[(size_t)(r0 + g + 8) * N + c0] = make_float2(c[mt][nt][2], c[mt][nt][3]);
            }
        }
    }
}

// ---------------- fused RMSNorm + RoPE (in place on half g_qkv q/k slices) ----------------
__global__ void __launch_bounds__(128) norm_rope_kernel(
    const float* __restrict__ qw, const float* __restrict__ kw)
{
    int rid = blockIdx.x;
    int tid = threadIdx.x;
    __half* buf;
    const float* w;
    int t;
    if (rid < T_TOK * NH) {
        t = rid / NH;
        int h = rid % NH;
        buf = g_qkv + (size_t)t * QKVS + (size_t)h * HD;
        w = qw;
    } else {
        rid -= T_TOK * NH;
        t = rid / NKV;
        int h = rid % NKV;
        buf = g_qkv + (size_t)t * QKVS + 4096 + (size_t)h * HD;
        w = kw;
    }
    float x = __half2float(buf[tid]);
    float s = x * x;
#pragma unroll
    for (int o = 16; o > 0; o >>= 1) s += __shfl_xor_sync(0xffffffffu, s, o);
    __shared__ float ws[4];
    __shared__ float sh[128];
    if ((tid & 31) == 0) ws[tid >> 5] = s;
    __syncthreads();
    s = ws[0] + ws[1] + ws[2] + ws[3];
    float y = x * rsqrtf(s * (1.0f / 128.0f) + 1e-6f) * w[tid];
    sh[tid] = y;
    __syncthreads();
    float c = g_cos[(size_t)t * 64 + (tid & 63)];
    float sn = g_sin[(size_t)t * 64 + (tid & 63)];
    float rot = (tid < 64) ? -sh[tid + 64] : sh[tid - 64];
    buf[tid] = __float2half_rn(y * c + rot * sn);
}

// ---------------- fp16 tensor-core flash attention ----------------
// 128-thread blocks, 2 blocks/SM. Block: 32 q x 2 heads = 64 A-rows; K-tiles 64.
// Double-buffered K/V tiles + register-pipelined fragments.
#define AST_H 136
#define PST_H 72
#define KV_STAGE (64 * AST_H)
#define ATT_SMEM ((64*AST_H + 4*KV_STAGE + 4*16*PST_H) * 2)   // 96256 B -> 2 blocks/SM

__global__ void __launch_bounds__(128, 2) attn_f16_kernel() {
    extern __shared__ __half smh[];
    __half* Qs = smh;                        // [64][136]
    __half* Ks = Qs + 64 * AST_H;            // [2][64][136]
    __half* Vs = Ks + 2 * KV_STAGE;          // [2][64][136]
    __half* Pw = Vs + 2 * KV_STAGE;          // 4 x [16][72]

    const int qt = 63 - blockIdx.x;
    const int hp = blockIdx.y;
    const int kvh = hp >> 1;
    const int headBase = kvh * 4 + (hp & 1) * 2;
    const int b = blockIdx.z;
    const int tid = threadIdx.x;
    const int warp = tid >> 5, lane = tid & 31;
    const int g = lane >> 2, tq = lane & 3;
    const float scale = 0.08838834764831845f;

    __half* Ps = Pw + warp * 16 * PST_H;
    const int rloc0 = warp * 16 + g;
    const int q0 = qt * 32 + (rloc0 & 31);
    const int head = headBase + (rloc0 >> 5);

    const uint32_t qAddr = smem_u32(Qs) +
        (uint32_t)((warp * 16 + (lane & 15)) * AST_H) * 2 + ((lane & 16) ? 16u : 0u);
    const uint32_t kAddr0 = smem_u32(Ks) +
        (uint32_t)(((lane & 7) + ((lane & 16) >> 1)) * AST_H) * 2 + ((lane & 8) << 1);
    const uint32_t vAddr0 = smem_u32(Vs) +
        (uint32_t)(((lane & 7) + ((lane & 8) ? 8 : 0)) * AST_H) * 2 + ((lane & 16) ? 16u : 0u);
    const uint32_t pAddr = smem_u32(Ps) +
        (uint32_t)((lane & 15) * PST_H) * 2 + ((lane & 16) ? 16u : 0u);

    // ---- prologue: Q tile, then KV tile 0 ----
#pragma unroll
    for (int i = 0; i < 8; i++) {
        int e = tid + (i << 7);
        int r = e >> 4, ds = (e & 15) << 3;
        cp16s(smem_u32(&Qs[r * AST_H + ds]),
              &g_qkv[(size_t)(b * SEQ + qt * 32 + (r & 31)) * QKVS +
                     (size_t)(headBase + (r >> 5)) * HD + ds]);
    }
    asm volatile("cp.async.commit_group;\n");

    const int nkt = (qt * 32 + 31) / 64 + 1;

#pragma unroll
    for (int i = 0; i < 8; i++) {
        int e = tid + (i << 7);
        int r = e >> 4, ds = (e & 15) << 3;
        const size_t go = (size_t)(b * SEQ + r) * QKVS + (size_t)kvh * HD + ds;
        cp16s(smem_u32(&Ks[r * AST_H + ds]), &g_qkv[go + 4096]);
        cp16s(smem_u32(&Vs[r * AST_H + ds]), &g_qkv[go + 5120]);
    }
    asm volatile("cp.async.commit_group;\n");
    asm volatile("cp.async.wait_group 0;\n");
    __syncthreads();

    float m0 = -1e30f, m1 = -1e30f, l0 = 0.f, l1 = 0.f;
    float o[16][4];
#pragma unroll
    for (int nt = 0; nt < 16; nt++)
#pragma unroll
        for (int e = 0; e < 4; e++) o[nt][e] = 0.f;

    for (int kt = 0; kt < nkt; kt++) {
        if (kt + 1 < nkt) {
            const int nBase = (kt + 1) * 64;
            const uint32_t so = (uint32_t)(((kt + 1) & 1) * KV_STAGE) * 2;
#pragma unroll
            for (int i = 0; i < 8; i++) {
                int e = tid + (i << 7);
                int r = e >> 4, ds = (e & 15) << 3;
                const size_t go = (size_t)(b * SEQ + nBase + r) * QKVS + (size_t)kvh * HD + ds;
                cp16s(smem_u32(&Ks[r * AST_H + ds]) + so, &g_qkv[go + 4096]);
                cp16s(smem_u32(&Vs[r * AST_H + ds]) + so, &g_qkv[go + 5120]);
            }
            asm volatile("cp.async.commit_group;\n");
        }

        const int kBase = kt * 64;
        const uint32_t so = (uint32_t)((kt & 1) * KV_STAGE) * 2;
        const uint32_t kAddr = kAddr0 + so;
        const uint32_t vAddr = vAddr0 + so;

        // ---- S = Q K^T (register-pipelined) ----
        float s[8][4];
#pragma unroll
        for (int nt = 0; nt < 8; nt++)
#pragma unroll
            for (int e = 0; e < 4; e++) s[nt][e] = 0.f;

        unsigned qa[2][4];
        ldsm4(qa[0][0], qa[0][1], qa[0][2], qa[0][3], qAddr);
#pragma unroll
        for (int ks = 0; ks < 8; ks++) {
            const int cq = ks & 1;
            unsigned kb[2][4];
            ldsm4(kb[0][0], kb[0][1], kb[0][2], kb[0][3],
                  kAddr + (uint32_t)(ks * 32));
#pragma unroll
            for (int p = 0; p < 4; p++) {
                const int bb = p & 1;
                if (p < 3) {
                    ldsm4(kb[bb ^ 1][0], kb[bb ^ 1][1], kb[bb ^ 1][2], kb[bb ^ 1][3],
                          kAddr + (uint32_t)((p + 1) * 16 * AST_H * 2 + ks * 32));
                } else if (ks < 7) {
                    ldsm4(qa[cq ^ 1][0], qa[cq ^ 1][1], qa[cq ^ 1][2], qa[cq ^ 1][3],
                          qAddr + (uint32_t)((ks + 1) * 32));
                }
                mma_f16(s[2*p][0], s[2*p][1], s[2*p][2], s[2*p][3],
                        qa[cq][0], qa[cq][1], qa[cq][2], qa[cq][3],
                        kb[bb][0], kb[bb][1]);
                mma_f16(s[2*p+1][0], s[2*p+1][1], s[2*p+1][2], s[2*p+1][3],
                        qa[cq][0], qa[cq][1], qa[cq][2], qa[cq][3],
                        kb[bb][2], kb[bb][3]);
            }
        }

        // ---- scale + causal mask ----
        const bool edge = (kBase + 63 > qt * 32);
#pragma unroll
        for (int nt = 0; nt < 8; nt++) {
            int c0 = kBase + nt * 8 + tq * 2;
            s[nt][0] *= scale; s[nt][1] *= scale;
            s[nt][2] *= scale; s[nt][3] *= scale;
            if (edge) {
                if (c0     > q0)     s[nt][0] = -1e30f;
                if (c0 + 1 > q0)     s[nt][1] = -1e30f;
                if (c0     > q0 + 8) s[nt][2] = -1e30f;
                if (c0 + 1 > q0 + 8) s[nt][3] = -1e30f;
            }
        }

        // ---- online softmax ----
        float mx0 = -1e30f, mx1 = -1e30f;
#pragma unroll
        for (int nt = 0; nt < 8; nt++) {
            mx0 = fmaxf(mx0, fmaxf(s[nt][0], s[nt][1]));
            mx1 = fmaxf(mx1, fmaxf(s[nt][2], s[nt][3]));
        }
        mx0 = fmaxf(mx0, __shfl_xor_sync(0xffffffffu, mx0, 1));
        mx0 = fmaxf(mx0, __shfl_xor_sync(0xffffffffu, mx0, 2));
        mx1 = fmaxf(mx1, __shfl_xor_sync(0xffffffffu, mx1, 1));
        mx1 = fmaxf(mx1, __shfl_xor_sync(0xffffffffu, mx1, 2));

        float mn0 = fmaxf(m0, mx0), mn1 = fmaxf(m1, mx1);
        float al0 = __expf(m0 - mn0), al1 = __expf(m1 - mn1);
        m0 = mn0; m1 = mn1;

        float ps0 = 0.f, ps1 = 0.f;
#pragma unroll
        for (int nt = 0; nt < 8; nt++) {
            float p0 = __expf(s[nt][0] - mn0);
            float p1 = __expf(s[nt][1] - mn0);
            float p2 = __expf(s[nt][2] - mn1);
            float p3 = __expf(s[nt][3] - mn1);
            ps0 += p0 + p1; ps1 += p2 + p3;
            int c0 = nt * 8 + tq * 2;
            *(__half2*)&Ps[(g)     * PST_H + c0] = __floats2half2_rn(p0, p1);
            *(__half2*)&Ps[(g + 8) * PST_H + c0] = __floats2half2_rn(p2, p3);
        }
        ps0 += __shfl_xor_sync(0xffffffffu, ps0, 1);
        ps0 += __shfl_xor_sync(0xffffffffu, ps0, 2);
        ps1 += __shfl_xor_sync(0xffffffffu, ps1, 1);
        ps1 += __shfl_xor_sync(0xffffffffu, ps1, 2);
        l0 = l0 * al0 + ps0;
        l1 = l1 * al1 + ps1;

#pragma unroll
        for (int nt = 0; nt < 16; nt++) {
            o[nt][0] *= al0; o[nt][1] *= al0;
            o[nt][2] *= al1; o[nt][3] *= al1;
        }
        __syncwarp();

        // ---- O += P V (register-pipelined) ----
        unsigned pa[2][4];
        ldsm4(pa[0][0], pa[0][1], pa[0][2], pa[0][3], pAddr);
#pragma unroll
        for (int ks = 0; ks < 4; ks++) {
            const int cq = ks & 1;
            const uint32_t vRow = vAddr + (uint32_t)(ks * 16 * AST_H * 2);
            unsigned vb[2][4];
            ldsm4t(vb[0][0], vb[0][1], vb[0][2], vb[0][3], vRow);
#pragma unroll
            for (int p = 0; p < 8; p++) {
                const int bb = p & 1;
                if (p < 7) {
                    ldsm4t(vb[bb ^ 1][0], vb[bb ^ 1][1], vb[bb ^ 1][2], vb[bb ^ 1][3],
                           vRow + (uint32_t)((p + 1) * 32));
                } else if (ks < 3) {
                    ldsm4(pa[cq ^ 1][0], pa[cq ^ 1][1], pa[cq ^ 1][2], pa[cq ^ 1][3],
                          pAddr + (uint32_t)((ks + 1) * 32));
                }
                mma_f16(o[2*p][0], o[2*p][1], o[2*p][2], o[2*p][3],
                        pa[cq][0], pa[cq][1], pa[cq][2], pa[cq][3],
                        vb[bb][0], vb[bb][1]);
                mma_f16(o[2*p+1][0], o[2*p+1][1], o[2*p+1][2], o[2*p+1][3],
                        pa[cq][0], pa[cq][1], pa[cq][2], pa[cq][3],
                        vb[bb][2], vb[bb][3]);
            }
        }

        if (kt + 1 < nkt) {
            asm volatile("cp.async.wait_group 0;\n");
            __syncthreads();
        }
    }

    // ---- epilogue (half output for final GEMM) ----
    float inv0 = 1.0f / l0, inv1 = 1.0f / l1;
    const size_t r0off = (size_t)(b * SEQ + q0) * QDIM + (size_t)head * HD;
    const size_t r1off = r0off + 8 * QDIM;
#pragma unroll
    for (int nt = 0; nt < 16; nt++) {
        int c0 = nt * 8 + tq * 2;
        *(__half2*)&g_ao[r0off + c0] = __floats2half2_rn(o[nt][0] * inv0, o[nt][1] * inv0);
        *(__half2*)&g_ao[r1off + c0] = __floats2half2_rn(o[nt][2] * inv1, o[nt][3] * inv1);
    }
}

// ---------------- launch ----------------
extern "C" void kernel_launch(void* const* d_in, const int* in_sizes, int n_in,
                              void* d_out, int out_size) {
    const float* hid = (const float*)d_in[0];
    const int*   pos = (const int*)d_in[1];
    const float* Wq  = (const float*)d_in[2];
    const float* Wk  = (const float*)d_in[3];
    const float* Wv  = (const float*)d_in[4];
    const float* Wo  = (const float*)d_in[5];
    const float* qw  = (const float*)d_in[6];
    const float* kw  = (const float*)d_in[7];
    float* out = (float*)d_out;

    __half *hid_h, *wtall, *wot, *qkv, *ao;
    cudaGetSymbolAddress((void**)&hid_h, g_hid_h);
    cudaGetSymbolAddress((void**)&wtall, g_WtAll);
    cudaGetSymbolAddress((void**)&wot, g_WoT);
    cudaGetSymbolAddress((void**)&qkv, g_qkv);
    cudaGetSymbolAddress((void**)&ao, g_ao);

    cudaFuncSetAttribute(gemm_f16_kernel<__half>, cudaFuncAttributeMaxDynamicSharedMemorySize, GEMM_SMEM);
    cudaFuncSetAttribute(gemm_f16_kernel<float>, cudaFuncAttributeMaxDynamicSharedMemorySize, GEMM_SMEM);
    cudaFuncSetAttribute(attn_f16_kernel, cudaFuncAttributeMaxDynamicSharedMemorySize, ATT_SMEM);

    // hidden -> fp16
    {
        int n4 = T_TOK * HIDN / 4;
        conv_half_kernel<<<(n4 + 255) / 256, 256>>>((const float4*)hid, (__half2*)hid_h, n4);
    }
    // all 4 weight transposes in one launch
    transpose_all_kernel<<<TRANS_BLOCKS, 256>>>(Wq, Wk, Wv, Wo);
    rope_table_kernel<<<(T_TOK * 64) / 256, 256>>>(pos);

    // fused QKV projection: [4096,2560] @ [6144,2560]^T -> half [4096,6144]
    gemm_f16_kernel<__half><<<dim3(QKVS / TN, T_TOK / TM), 128, GEMM_SMEM>>>(
        hid_h, wtall, qkv, T_TOK, QKVS, HIDN);

    norm_rope_kernel<<<T_TOK * (NH + NKV), 128>>>(qw, kw);

    // attention: 2 heads per block, 2 blocks/SM, double-buffered K/V
    attn_f16_kernel<<<dim3(64, NKV * 2, BATCH), 128, ATT_SMEM>>>();

    // output projection: [4096,4096] @ [2560,4096]^T -> fp32 out [4096,2560]
    gemm_f16_kernel<float><<<dim3(HIDN / TN, T_TOK / TM), 128, GEMM_SMEM>>>(
        ao, wot, out, T_TOK, HIDN, QDIM);
}

// round 16
// speedup vs baseline: 1.0721x; 1.0332x over previous
#include <cuda_runtime.h>
#include <cuda_fp16.h>
#include <math.h>
#include <stdint.h>

// ---------------- problem constants ----------------
#define BATCH 2
#define SEQ   2048
#define T_TOK 4096
#define HIDN  2560
#define NH    32
#define NKV   8
#define HD    128
#define QDIM  4096
#define KVDIM 1024
#define QKVS  6144          // packed q|k|v row stride (halves)

// ---------------- scratch ----------------
__device__ __half g_hid_h[(size_t)T_TOK * HIDN];
__device__ __half g_WtAll[(size_t)QKVS * HIDN];   // WqT|WkT|WvT rows, each [*, 2560] K-major
__device__ __half g_WoT[(size_t)HIDN * QDIM];     // WoT [2560][4096] K-major
__device__ __half g_qkv[(size_t)T_TOK * QKVS];
__device__ __half g_ao[(size_t)T_TOK * QDIM];
__device__ float  g_cos[(size_t)T_TOK * 64];
__device__ float  g_sin[(size_t)T_TOK * 64];

// ---------------- helpers ----------------
__device__ __forceinline__ uint32_t smem_u32(const void* p) {
    uint32_t a;
    asm("{ .reg .u64 t; cvta.to.shared.u64 t, %1; cvt.u32.u64 %0, t; }" : "=r"(a) : "l"(p));
    return a;
}

__device__ __forceinline__ void cp16s(uint32_t saddr, const void* gsrc) {
    asm volatile("cp.async.cg.shared.global [%0], [%1], 16;\n" :: "r"(saddr), "l"(gsrc));
}

__device__ __forceinline__ void ldsm4(unsigned& r0, unsigned& r1, unsigned& r2, unsigned& r3,
                                      uint32_t addr) {
    asm volatile("ldmatrix.sync.aligned.m8n8.x4.shared.b16 {%0,%1,%2,%3}, [%4];"
                 : "=r"(r0), "=r"(r1), "=r"(r2), "=r"(r3) : "r"(addr));
}

__device__ __forceinline__ void ldsm4t(unsigned& r0, unsigned& r1, unsigned& r2, unsigned& r3,
                                       uint32_t addr) {
    asm volatile("ldmatrix.sync.aligned.m8n8.x4.trans.shared.b16 {%0,%1,%2,%3}, [%4];"
                 : "=r"(r0), "=r"(r1), "=r"(r2), "=r"(r3) : "r"(addr));
}

// m16n8k16 fp16 mma, fp32 accumulate
__device__ __forceinline__ void mma_f16(
    float& d0, float& d1, float& d2, float& d3,
    unsigned a0, unsigned a1, unsigned a2, unsigned a3,
    unsigned b0, unsigned b1)
{
    asm volatile(
        "mma.sync.aligned.m16n8k16.row.col.f32.f16.f16.f32 "
        "{%0,%1,%2,%3},{%4,%5,%6,%7},{%8,%9},{%0,%1,%2,%3};"
        : "+f"(d0), "+f"(d1), "+f"(d2), "+f"(d3)
        : "r"(a0), "r"(a1), "r"(a2), "r"(a3), "r"(b0), "r"(b1));
}

// ---------------- fp32 -> fp16 conversion ----------------
__global__ void conv_half_kernel(const float4* __restrict__ in, __half2* __restrict__ out, int n4) {
    int i = blockIdx.x * blockDim.x + threadIdx.x;
    int stride = gridDim.x * blockDim.x;
    for (; i < n4; i += stride) {
        float4 v = in[i];
        out[2 * i]     = __floats2half2_rn(v.x, v.y);
        out[2 * i + 1] = __floats2half2_rn(v.z, v.w);
    }
}

// ---------------- combined weight transpose + fp16 (all 4 weights, one launch) ----------
#define TRANS_BLOCKS 25600
__global__ void __launch_bounds__(256) transpose_all_kernel(
    const float* __restrict__ Wq, const float* __restrict__ Wk,
    const float* __restrict__ Wv, const float* __restrict__ Wo)
{
    int bid = blockIdx.x;
    const float* in;
    __half* out;
    int R, C;
    if (bid < 10240)      { in = Wq; out = g_WtAll;                         R = HIDN; C = QDIM;  }
    else if (bid < 12800) { in = Wk; out = g_WtAll + (size_t)4096 * HIDN;   R = HIDN; C = KVDIM; bid -= 10240; }
    else if (bid < 15360) { in = Wv; out = g_WtAll + (size_t)5120 * HIDN;   R = HIDN; C = KVDIM; bid -= 12800; }
    else                  { in = Wo; out = g_WoT;                           R = QDIM; C = HIDN;  bid -= 15360; }
    const int nbx = C / 32;
    const int bc = (bid % nbx) * 32, br = (bid / nbx) * 32;

    __shared__ float t[32][33];
    const int tx = threadIdx.x & 31, ty = threadIdx.x >> 5;   // 32 x 8
#pragma unroll
    for (int i = 0; i < 32; i += 8)
        t[ty + i][tx] = in[(size_t)(br + ty + i) * C + bc + tx];
    __syncthreads();
#pragma unroll
    for (int i = 0; i < 32; i += 8)
        out[(size_t)(bc + ty + i) * R + br + tx] = __float2half_rn(t[tx][ty + i]);
}

// ---------------- RoPE cos/sin table ----------------
__global__ void rope_table_kernel(const int* __restrict__ p32) {
    int idx = blockIdx.x * blockDim.x + threadIdx.x;
    if (idx >= T_TOK * 64) return;
    int t = idx >> 6;
    int i = idx & 63;
    bool is64 = (p32[1] == 0 && p32[2] == 1);
    int pos = is64 ? p32[2 * t] : p32[t];
    double ang = (double)pos * exp(-(double)i * (log(1000000.0) / 64.0));
    g_cos[idx] = (float)cos(ang);
    g_sin[idx] = (float)sin(ang);
}

// ---------------- fp16 mma GEMM (persistent grid-stride over tiles) ----------------
// 128-thread blocks, 2 blocks/SM; block tile 128x128, 4 warps (2x2), warp tile
// 64x64, K-chunk 64, 3-stage cp.async pipeline. Grid = 296 persistent blocks;
// each loops over tiles -> no wave quantization.
#define TM 128
#define TN 128
#define GSTH 72
#define A_STAGE (TM * GSTH * 2)                 // 18432 B
#define STAGE_BYTES ((TM + TN) * GSTH * 2)      // 36864 B
#define GEMM_SMEM (3 * STAGE_BYTES)             // 110592 B -> 2 blocks/SM
#define PERSIST_BLOCKS 296

__device__ __forceinline__ void g_load(
    const __half* __restrict__ A, const __half* __restrict__ Bt, int K,
    int mBase, int nBase, int kc, uint32_t stage, int tid)
{
    const uint32_t sA = stage, sB = stage + A_STAGE;
    const __half* Ag = A + (size_t)mBase * K + (size_t)kc * 64;
#pragma unroll
    for (int i = 0; i < 8; i++) {
        int e = tid + i * 128;
        int r = e >> 3, q = (e & 7) << 3;
        cp16s(sA + (uint32_t)(r * GSTH + q) * 2, Ag + (size_t)r * K + q);
    }
    const __half* Bg = Bt + (size_t)nBase * K + (size_t)kc * 64;
#pragma unroll
    for (int i = 0; i < 8; i++) {
        int e = tid + i * 128;
        int r = e >> 3, q = (e & 7) << 3;
        cp16s(sB + (uint32_t)(r * GSTH + q) * 2, Bg + (size_t)r * K + q);
    }
    asm volatile("cp.async.commit_group;\n");
}

template <typename OutT>
__global__ void __launch_bounds__(128, 2) gemm_f16_kernel(
    const __half* __restrict__ A, const __half* __restrict__ Bt, OutT* __restrict__ C,
    int M, int N, int K)
{
    extern __shared__ char smem[];
    const uint32_t sb = smem_u32(smem);
    const int tid = threadIdx.x, warp = tid >> 5, lane = tid & 31;
    const int wm = warp >> 1, wn = warp & 1;
    const int g = lane >> 2, tq = lane & 3;

    const uint32_t aFragOff =
        (uint32_t)((wm * 64 + (lane & 15)) * GSTH) * 2 + ((lane & 16) ? 16u : 0u);
    const uint32_t bFragOff =
        (uint32_t)((wn * 64 + (lane & 7) + ((lane & 16) >> 1)) * GSTH) * 2 + ((lane & 8) << 1);

    const int nk = K >> 6;
    const int ntx = N / TN;
    const int numTiles = (M / TM) * ntx;

    for (int tile = blockIdx.x; tile < numTiles; tile += gridDim.x) {
        const int mBase = (tile / ntx) * TM;
        const int nBase = (tile % ntx) * TN;

        float c[4][8][4];
#pragma unroll
        for (int mt = 0; mt < 4; mt++)
#pragma unroll
            for (int nt = 0; nt < 8; nt++)
#pragma unroll
                for (int e = 0; e < 4; e++) c[mt][nt][e] = 0.f;

        g_load(A, Bt, K, mBase, nBase, 0, sb, tid);
        g_load(A, Bt, K, mBase, nBase, 1, sb + STAGE_BYTES, tid);

        uint32_t stage = 0;
        for (int i = 0; i < nk; i++) {
            if (i + 1 < nk) {
                asm volatile("cp.async.wait_group 1;\n");
            } else {
                asm volatile("cp.async.wait_group 0;\n");
            }
            __syncthreads();
            if (i + 2 < nk) {
                uint32_t nxt = stage + 2 * STAGE_BYTES;
                if (nxt >= 3 * STAGE_BYTES) nxt -= 3 * STAGE_BYTES;
                g_load(A, Bt, K, mBase, nBase, i + 2, sb + nxt, tid);
            }

            const uint32_t stA = sb + stage;
            const uint32_t stB = stA + A_STAGE;

            unsigned a[2][4][4];
#pragma unroll
            for (int mt = 0; mt < 4; mt++)
                ldsm4(a[0][mt][0], a[0][mt][1], a[0][mt][2], a[0][mt][3],
                      stA + aFragOff + (uint32_t)(mt * 16 * GSTH * 2));
#pragma unroll
            for (int ks = 0; ks < 4; ks++) {
                const int cq = ks & 1;
                unsigned b[2][4];
                ldsm4(b[0][0], b[0][1], b[0][2], b[0][3],
                      stB + bFragOff + (uint32_t)(ks * 32));
#pragma unroll
                for (int p = 0; p < 4; p++) {
                    const int bb = p & 1;
                    if (p < 3) {
                        ldsm4(b[bb ^ 1][0], b[bb ^ 1][1], b[bb ^ 1][2], b[bb ^ 1][3],
                              stB + bFragOff + (uint32_t)((p + 1) * 16 * GSTH * 2 + ks * 32));
                    } else if (ks < 3) {
#pragma unroll
                        for (int mt = 0; mt < 4; mt++)
                            ldsm4(a[cq ^ 1][mt][0], a[cq ^ 1][mt][1],
                                  a[cq ^ 1][mt][2], a[cq ^ 1][mt][3],
                                  stA + aFragOff + (uint32_t)(mt * 16 * GSTH * 2 + (ks + 1) * 32));
                    }
#pragma unroll
                    for (int mt = 0; mt < 4; mt++) {
                        mma_f16(c[mt][2*p][0], c[mt][2*p][1], c[mt][2*p][2], c[mt][2*p][3],
                                a[cq][mt][0], a[cq][mt][1], a[cq][mt][2], a[cq][mt][3],
                                b[bb][0], b[bb][1]);
                        mma_f16(c[mt][2*p+1][0], c[mt][2*p+1][1], c[mt][2*p+1][2], c[mt][2*p+1][3],
                                a[cq][mt][0], a[cq][mt][1], a[cq][mt][2], a[cq][mt][3],
                                b[bb][2], b[bb][3]);
                    }
                }
            }
            stage += STAGE_BYTES;
            if (stage >= 3 * STAGE_BYTES) stage = 0;
        }

        // epilogue
#pragma unroll
        for (int mt = 0; mt < 4; mt++) {
            const int r0 = mBase + wm * 64 + mt * 16;
#pragma unroll
            for (int nt = 0; nt < 8; nt++) {
                const int c0 = nBase + wn * 64 + nt * 8 + tq * 2;
                if constexpr (sizeof(OutT) == 2) {
                    *(__half2*)&C[(size_t)(r0 + g)     * N + c0] =
                        __floats2half2_rn(c[mt][nt][0], c[mt][nt][1]);
                    *(__half2*)&C[(size_t)(r0 + g + 8) * N + c0] =
                        __floats2half2_rn(c[mt][nt][2], c[mt][nt][3]);
                } else {
                    *(float2*)&C[(size_t)(r0 + g)     * N + c0] = make_float2(c[mt][nt][0], c[mt][nt][1]);
                    *(float2*)&C[(size_t)(r0 + g + 8) * N + c0] = make_float2(c[mt][nt][2], c[mt][nt][3]);
                }
            }
        }
        __syncthreads();   // smem reuse across tiles
    }
}

// ---------------- fused RMSNorm + RoPE (in place on half g_qkv q/k slices) ----------------
__global__ void __launch_bounds__(128) norm_rope_kernel(
    const float* __restrict__ qw, const float* __restrict__ kw)
{
    int rid = blockIdx.x;
    int tid = threadIdx.x;
    __half* buf;
    const float* w;
    int t;
    if (rid < T_TOK * NH) {
        t = rid / NH;
        int h = rid % NH;
        buf = g_qkv + (size_t)t * QKVS + (size_t)h * HD;
        w = qw;
    } else {
        rid -= T_TOK * NH;
        t = rid / NKV;
        int h = rid % NKV;
        buf = g_qkv + (size_t)t * QKVS + 4096 + (size_t)h * HD;
        w = kw;
    }
    float x = __half2float(buf[tid]);
    float s = x * x;
#pragma unroll
    for (int o = 16; o > 0; o >>= 1) s += __shfl_xor_sync(0xffffffffu, s, o);
    __shared__ float ws[4];
    __shared__ float sh[128];
    if ((tid & 31) == 0) ws[tid >> 5] = s;
    __syncthreads();
    s = ws[0] + ws[1] + ws[2] + ws[3];
    float y = x * rsqrtf(s * (1.0f / 128.0f) + 1e-6f) * w[tid];
    sh[tid] = y;
    __syncthreads();
    float c = g_cos[(size_t)t * 64 + (tid & 63)];
    float sn = g_sin[(size_t)t * 64 + (tid & 63)];
    float rot = (tid < 64) ? -sh[tid + 64] : sh[tid - 64];
    buf[tid] = __float2half_rn(y * c + rot * sn);
}

// ---------------- fp16 tensor-core flash attention ----------------
// 128-thread blocks, 2 blocks/SM. Block: 32 q x 2 heads = 64 A-rows; K-tiles 64.
// Double-buffered K/V tiles + register-pipelined fragments.
#define AST_H 136
#define PST_H 72
#define KV_STAGE (64 * AST_H)
#define ATT_SMEM ((64*AST_H + 4*KV_STAGE + 4*16*PST_H) * 2)   // 96256 B -> 2 blocks/SM

__global__ void __launch_bounds__(128, 2) attn_f16_kernel() {
    extern __shared__ __half smh[];
    __half* Qs = smh;                        // [64][136]
    __half* Ks = Qs + 64 * AST_H;            // [2][64][136]
    __half* Vs = Ks + 2 * KV_STAGE;          // [2][64][136]
    __half* Pw = Vs + 2 * KV_STAGE;          // 4 x [16][72]

    const int qt = 63 - blockIdx.x;
    const int hp = blockIdx.y;
    const int kvh = hp >> 1;
    const int headBase = kvh * 4 + (hp & 1) * 2;
    const int b = blockIdx.z;
    const int tid = threadIdx.x;
    const int warp = tid >> 5, lane = tid & 31;
    const int g = lane >> 2, tq = lane & 3;
    const float scale = 0.08838834764831845f;

    __half* Ps = Pw + warp * 16 * PST_H;
    const int rloc0 = warp * 16 + g;
    const int q0 = qt * 32 + (rloc0 & 31);
    const int head = headBase + (rloc0 >> 5);

    const uint32_t qAddr = smem_u32(Qs) +
        (uint32_t)((warp * 16 + (lane & 15)) * AST_H) * 2 + ((lane & 16) ? 16u : 0u);
    const uint32_t kAddr0 = smem_u32(Ks) +
        (uint32_t)(((lane & 7) + ((lane & 16) >> 1)) * AST_H) * 2 + ((lane & 8) << 1);
    const uint32_t vAddr0 = smem_u32(Vs) +
        (uint32_t)(((lane & 7) + ((lane & 8) ? 8 : 0)) * AST_H) * 2 + ((lane & 16) ? 16u : 0u);
    const uint32_t pAddr = smem_u32(Ps) +
        (uint32_t)((lane & 15) * PST_H) * 2 + ((lane & 16) ? 16u : 0u);

    // ---- prologue: Q tile, then KV tile 0 ----
#pragma unroll
    for (int i = 0; i < 8; i++) {
        int e = tid + (i << 7);
        int r = e >> 4, ds = (e & 15) << 3;
        cp16s(smem_u32(&Qs[r * AST_H + ds]),
              &g_qkv[(size_t)(b * SEQ + qt * 32 + (r & 31)) * QKVS +
                     (size_t)(headBase + (r >> 5)) * HD + ds]);
    }
    asm volatile("cp.async.commit_group;\n");

    const int nkt = (qt * 32 + 31) / 64 + 1;

#pragma unroll
    for (int i = 0; i < 8; i++) {
        int e = tid + (i << 7);
        int r = e >> 4, ds = (e & 15) << 3;
        const size_t go = (size_t)(b * SEQ + r) * QKVS + (size_t)kvh * HD + ds;
        cp16s(smem_u32(&Ks[r * AST_H + ds]), &g_qkv[go + 4096]);
        cp16s(smem_u32(&Vs[r * AST_H + ds]), &g_qkv[go + 5120]);
    }
    asm volatile("cp.async.commit_group;\n");
    asm volatile("cp.async.wait_group 0;\n");
    __syncthreads();

    float m0 = -1e30f, m1 = -1e30f, l0 = 0.f, l1 = 0.f;
    float o[16][4];
#pragma unroll
    for (int nt = 0; nt < 16; nt++)
#pragma unroll
        for (int e = 0; e < 4; e++) o[nt][e] = 0.f;

    for (int kt = 0; kt < nkt; kt++) {
        if (kt + 1 < nkt) {
            const int nBase = (kt + 1) * 64;
            const uint32_t so = (uint32_t)(((kt + 1) & 1) * KV_STAGE) * 2;
#pragma unroll
            for (int i = 0; i < 8; i++) {
                int e = tid + (i << 7);
                int r = e >> 4, ds = (e & 15) << 3;
                const size_t go = (size_t)(b * SEQ + nBase + r) * QKVS + (size_t)kvh * HD + ds;
                cp16s(smem_u32(&Ks[r * AST_H + ds]) + so, &g_qkv[go + 4096]);
                cp16s(smem_u32(&Vs[r * AST_H + ds]) + so, &g_qkv[go + 5120]);
            }
            asm volatile("cp.async.commit_group;\n");
        }

        const int kBase = kt * 64;
        const uint32_t so = (uint32_t)((kt & 1) * KV_STAGE) * 2;
        const uint32_t kAddr = kAddr0 + so;
        const uint32_t vAddr = vAddr0 + so;

        // ---- S = Q K^T (register-pipelined) ----
        float s[8][4];
#pragma unroll
        for (int nt = 0; nt < 8; nt++)
#pragma unroll
            for (int e = 0; e < 4; e++) s[nt][e] = 0.f;

        unsigned qa[2][4];
        ldsm4(qa[0][0], qa[0][1], qa[0][2], qa[0][3], qAddr);
#pragma unroll
        for (int ks = 0; ks < 8; ks++) {
            const int cq = ks & 1;
            unsigned kb[2][4];
            ldsm4(kb[0][0], kb[0][1], kb[0][2], kb[0][3],
                  kAddr + (uint32_t)(ks * 32));
#pragma unroll
            for (int p = 0; p < 4; p++) {
                const int bb = p & 1;
                if (p < 3) {
                    ldsm4(kb[bb ^ 1][0], kb[bb ^ 1][1], kb[bb ^ 1][2], kb[bb ^ 1][3],
                          kAddr + (uint32_t)((p + 1) * 16 * AST_H * 2 + ks * 32));
                } else if (ks < 7) {
                    ldsm4(qa[cq ^ 1][0], qa[cq ^ 1][1], qa[cq ^ 1][2], qa[cq ^ 1][3],
                          qAddr + (uint32_t)((ks + 1) * 32));
                }
                mma_f16(s[2*p][0], s[2*p][1], s[2*p][2], s[2*p][3],
                        qa[cq][0], qa[cq][1], qa[cq][2], qa[cq][3],
                        kb[bb][0], kb[bb][1]);
                mma_f16(s[2*p+1][0], s[2*p+1][1], s[2*p+1][2], s[2*p+1][3],
                        qa[cq][0], qa[cq][1], qa[cq][2], qa[cq][3],
                        kb[bb][2], kb[bb][3]);
            }
        }

        // ---- scale + causal mask ----
        const bool edge = (kBase + 63 > qt * 32);
#pragma unroll
        for (int nt = 0; nt < 8; nt++) {
            int c0 = kBase + nt * 8 + tq * 2;
            s[nt][0] *= scale; s[nt][1] *= scale;
            s[nt][2] *= scale; s[nt][3] *= scale;
            if (edge) {
                if (c0     > q0)     s[nt][0] = -1e30f;
                if (c0 + 1 > q0)     s[nt][1] = -1e30f;
                if (c0     > q0 + 8) s[nt][2] = -1e30f;
                if (c0 + 1 > q0 + 8) s[nt][3] = -1e30f;
            }
        }

        // ---- online softmax ----
        float mx0 = -1e30f, mx1 = -1e30f;
#pragma unroll
        for (int nt = 0; nt < 8; nt++) {
            mx0 = fmaxf(mx0, fmaxf(s[nt][0], s[nt][1]));
            mx1 = fmaxf(mx1, fmaxf(s[nt][2], s[nt][3]));
        }
        mx0 = fmaxf(mx0, __shfl_xor_sync(0xffffffffu, mx0, 1));
        mx0 = fmaxf(mx0, __shfl_xor_sync(0xffffffffu, mx0, 2));
        mx1 = fmaxf(mx1, __shfl_xor_sync(0xffffffffu, mx1, 1));
        mx1 = fmaxf(mx1, __shfl_xor_sync(0xffffffffu, mx1, 2));

        float mn0 = fmaxf(m0, mx0), mn1 = fmaxf(m1, mx1);
        float al0 = __expf(m0 - mn0), al1 = __expf(m1 - mn1);
        m0 = mn0; m1 = mn1;

        float ps0 = 0.f, ps1 = 0.f;
#pragma unroll
        for (int nt = 0; nt < 8; nt++) {
            float p0 = __expf(s[nt][0] - mn0);
            float p1 = __expf(s[nt][1] - mn0);
            float p2 = __expf(s[nt][2] - mn1);
            float p3 = __expf(s[nt][3] - mn1);
            ps0 += p0 + p1; ps1 += p2 + p3;
            int c0 = nt * 8 + tq * 2;
            *(__half2*)&Ps[(g)     * PST_H + c0] = __floats2half2_rn(p0, p1);
            *(__half2*)&Ps[(g + 8) * PST_H + c0] = __floats2half2_rn(p2, p3);
        }
        ps0 += __shfl_xor_sync(0xffffffffu, ps0, 1);
        ps0 += __shfl_xor_sync(0xffffffffu, ps0, 2);
        ps1 += __shfl_xor_sync(0xffffffffu, ps1, 1);
        ps1 += __shfl_xor_sync(0xffffffffu, ps1, 2);
        l0 = l0 * al0 + ps0;
        l1 = l1 * al1 + ps1;

#pragma unroll
        for (int nt = 0; nt < 16; nt++) {
            o[nt][0] *= al0; o[nt][1] *= al0;
            o[nt][2] *= al1; o[nt][3] *= al1;
        }
        __syncwarp();

        // ---- O += P V (register-pipelined) ----
        unsigned pa[2][4];
        ldsm4(pa[0][0], pa[0][1], pa[0][2], pa[0][3], pAddr);
#pragma unroll
        for (int ks = 0; ks < 4; ks++) {
            const int cq = ks & 1;
            const uint32_t vRow = vAddr + (uint32_t)(ks * 16 * AST_H * 2);
            unsigned vb[2][4];
            ldsm4t(vb[0][0], vb[0][1], vb[0][2], vb[0][3], vRow);
#pragma unroll
            for (int p = 0; p < 8; p++) {
                const int bb = p & 1;
                if (p < 7) {
                    ldsm4t(vb[bb ^ 1][0], vb[bb ^ 1][1], vb[bb ^ 1][2], vb[bb ^ 1][3],
                           vRow + (uint32_t)((p + 1) * 32));
                } else if (ks < 3) {
                    ldsm4(pa[cq ^ 1][0], pa[cq ^ 1][1], pa[cq ^ 1][2], pa[cq ^ 1][3],
                          pAddr + (uint32_t)((ks + 1) * 32));
                }
                mma_f16(o[2*p][0], o[2*p][1], o[2*p][2], o[2*p][3],
                        pa[cq][0], pa[cq][1], pa[cq][2], pa[cq][3],
                        vb[bb][0], vb[bb][1]);
                mma_f16(o[2*p+1][0], o[2*p+1][1], o[2*p+1][2], o[2*p+1][3],
                        pa[cq][0], pa[cq][1], pa[cq][2], pa[cq][3],
                        vb[bb][2], vb[bb][3]);
            }
        }

        if (kt + 1 < nkt) {
            asm volatile("cp.async.wait_group 0;\n");
            __syncthreads();
        }
    }

    // ---- epilogue (half output for final GEMM) ----
    float inv0 = 1.0f / l0, inv1 = 1.0f / l1;
    const size_t r0off = (size_t)(b * SEQ + q0) * QDIM + (size_t)head * HD;
    const size_t r1off = r0off + 8 * QDIM;
#pragma unroll
    for (int nt = 0; nt < 16; nt++) {
        int c0 = nt * 8 + tq * 2;
        *(__half2*)&g_ao[r0off + c0] = __floats2half2_rn(o[nt][0] * inv0, o[nt][1] * inv0);
        *(__half2*)&g_ao[r1off + c0] = __floats2half2_rn(o[nt][2] * inv1, o[nt][3] * inv1);
    }
}

// ---------------- launch ----------------
extern "C" void kernel_launch(void* const* d_in, const int* in_sizes, int n_in,
                              void* d_out, int out_size) {
    const float* hid = (const float*)d_in[0];
    const int*   pos = (const int*)d_in[1];
    const float* Wq  = (const float*)d_in[2];
    const float* Wk  = (const float*)d_in[3];
    const float* Wv  = (const float*)d_in[4];
    const float* Wo  = (const float*)d_in[5];
    const float* qw  = (const float*)d_in[6];
    const float* kw  = (const float*)d_in[7];
    float* out = (float*)d_out;

    __half *hid_h, *wtall, *wot, *qkv, *ao;
    cudaGetSymbolAddress((void**)&hid_h, g_hid_h);
    cudaGetSymbolAddress((void**)&wtall, g_WtAll);
    cudaGetSymbolAddress((void**)&wot, g_WoT);
    cudaGetSymbolAddress((void**)&qkv, g_qkv);
    cudaGetSymbolAddress((void**)&ao, g_ao);

    cudaFuncSetAttribute(gemm_f16_kernel<__half>, cudaFuncAttributeMaxDynamicSharedMemorySize, GEMM_SMEM);
    cudaFuncSetAttribute(gemm_f16_kernel<float>, cudaFuncAttributeMaxDynamicSharedMemorySize, GEMM_SMEM);
    cudaFuncSetAttribute(attn_f16_kernel, cudaFuncAttributeMaxDynamicSharedMemorySize, ATT_SMEM);

    // hidden -> fp16
    {
        int n4 = T_TOK * HIDN / 4;
        conv_half_kernel<<<(n4 + 255) / 256, 256>>>((const float4*)hid, (__half2*)hid_h, n4);
    }
    // all 4 weight transposes in one launch
    transpose_all_kernel<<<TRANS_BLOCKS, 256>>>(Wq, Wk, Wv, Wo);
    rope_table_kernel<<<(T_TOK * 64) / 256, 256>>>(pos);

    // fused QKV projection (persistent): [4096,2560] @ [6144,2560]^T -> half [4096,6144]
    gemm_f16_kernel<__half><<<PERSIST_BLOCKS, 128, GEMM_SMEM>>>(
        hid_h, wtall, qkv, T_TOK, QKVS, HIDN);

    norm_rope_kernel<<<T_TOK * (NH + NKV), 128>>>(qw, kw);

    // attention: 2 heads per block, 2 blocks/SM, double-buffered K/V
    attn_f16_kernel<<<dim3(64, NKV * 2, BATCH), 128, ATT_SMEM>>>();

    // output projection (persistent): [4096,4096] @ [2560,4096]^T -> fp32 out [4096,2560]
    gemm_f16_kernel<float><<<PERSIST_BLOCKS, 128, GEMM_SMEM>>>(
        ao, wot, out, T_TOK, HIDN, QDIM);
}